// round 12
// baseline (speedup 1.0000x reference)
#include <cuda_runtime.h>
#include <cuda_bf16.h>
#include <cstdint>

#define HW 65536
#define NB 8

// ---- scratch (__device__ globals; allocation is forbidden) ----
__device__ float g_sum[512], g_sq[512], g_pool[512], g_s2[512], g_q2[512];
__device__ float g_b1f[NB*128], g_b3f[NB*128];
__device__ __nv_bfloat16 g_w1f[NB*128*64], g_w3f[NB*128*64], g_w2f[NB*64*64], g_w4h[64*64];
__device__ __nv_bfloat16 g_y[(size_t)NB*64*HW];    // gate output (64 MB)
__device__ int g_cnt1[NB], g_cnt3[NB], g_cnt5[NB]; // zero-init; self-reset each use

__device__ __forceinline__ float warpsum(float v){
#pragma unroll
  for(int o=16;o>0;o>>=1) v += __shfl_down_sync(0xffffffffu, v, o);
  return v;
}

__device__ __forceinline__ void mma_bf16(float& d0,float& d1,float& d2,float& d3,
    uint32_t a0,uint32_t a1,uint32_t a2,uint32_t a3,uint32_t b0,uint32_t b1){
  asm volatile("mma.sync.aligned.m16n8k16.row.col.f32.bf16.bf16.f32 "
    "{%0,%1,%2,%3},{%4,%5,%6,%7},{%8,%9},{%0,%1,%2,%3};"
    : "+f"(d0),"+f"(d1),"+f"(d2),"+f"(d3)
    : "r"(a0),"r"(a1),"r"(a2),"r"(a3),"r"(b0),"r"(b1));
}

__device__ __forceinline__ uint32_t pkf(float a,float b){
  __nv_bfloat162 p=__floats2bfloat162_rn(a,b);
  return *(uint32_t*)&p;
}
#define PK2RAW(lo,hi) ((uint32_t)(*(const unsigned short*)&(lo)) | ((uint32_t)(*(const unsigned short*)&(hi))<<16))

// load A fragments (4 k-steps) from row-major bf16 [rows][64]
__device__ __forceinline__ void loadA(uint32_t A[4][4], const __nv_bfloat16* wf,
                                      int m0,int grp,int t4){
#pragma unroll
  for(int k=0;k<4;k++){
    int c0=k*16+2*t4;
    A[k][0]=*(const uint32_t*)(wf+(m0+grp)*64+c0);
    A[k][1]=*(const uint32_t*)(wf+(m0+grp+8)*64+c0);
    A[k][2]=*(const uint32_t*)(wf+(m0+grp)*64+c0+8);
    A[k][3]=*(const uint32_t*)(wf+(m0+grp+8)*64+c0+8);
  }
}

// ---------------- K1: stats of x + (last block per n) ln1->pw1 fold ----------------
__global__ __launch_bounds__(256) void k1(const float* __restrict__ x,
                                          const float* __restrict__ ln1w,const float* __restrict__ ln1b,
                                          const float* __restrict__ pw1w,const float* __restrict__ pw1b,
                                          const float* __restrict__ pw4w){
  int nc=blockIdx.x, n=nc>>6, tid=threadIdx.x;
  const float4* p=(const float4*)(x+(size_t)nc*HW);
  float s=0.f,q=0.f;
  for(int i=tid;i<HW/4;i+=256){
    float4 v=p[i];
    s+=(v.x+v.y)+(v.z+v.w);
    q+=v.x*v.x+v.y*v.y+v.z*v.z+v.w*v.w;
  }
  s=warpsum(s); q=warpsum(q);
  __shared__ float rs[8],rq[8];
  if((tid&31)==0){rs[tid>>5]=s;rq[tid>>5]=q;}
  __syncthreads();
  __shared__ int lastf;
  if(tid==0){
    float S=0,Q=0;
#pragma unroll
    for(int i=0;i<8;i++){S+=rs[i];Q+=rq[i];}
    g_sum[nc]=S; g_sq[nc]=Q;
    __threadfence();
    lastf=(atomicAdd(&g_cnt1[n],1)==63);
  }
  __syncthreads();
  if(!lastf) return;
  if(tid==0){ g_cnt1[n]=0; __threadfence(); }
  __shared__ float a[64], cc[64];
  if(tid<64){
    float mean=g_sum[n*64+tid]*(1.f/HW);
    float var =g_sq[n*64+tid]*(1.f/HW)-mean*mean;
    float ai=ln1w[tid]*rsqrtf(var+1e-6f);
    a[tid]=ai; cc[tid]=ln1b[tid]-mean*ai;
    g_pool[n*64+tid]=0.f;
  }
  __syncthreads();
  if(tid<128){
    int o=tid;
    float bacc=pw1b[o];
#pragma unroll 8
    for(int c=0;c<64;c++){
      float w=pw1w[o*64+c];
      bacc+=w*cc[c];
      g_w1f[(n*128+o)*64+c]=__float2bfloat16(w*a[c]);
    }
    g_b1f[n*128+o]=bacc;
  } else if(n==0 && tid<192){
    int o=tid-128;
    for(int c=0;c<64;c++) g_w4h[o*64+c]=__float2bfloat16(pw4w[o*64+c]);
  }
}

// ---------------- K3 (fused): pw1 GEMM + depthwise3x3 + gate + pool + SCA fold ----------------
#define TS_WORDS (64*344)
#define K3_SMEM (TS_WORDS*4 + 64*72*2 + 64*9*8 + 64*8)   // 102400 B

__device__ __forceinline__ bool pvalid(int p,int h0,int w0){
  int pr=p/34, pc=p-pr*34;
  int hh=h0-1+pr, wn=w0-1+pc;
  return ((unsigned)hh<256u)&&((unsigned)wn<256u);
}

__global__ __launch_bounds__(256) void k3(const float* __restrict__ x,
                                          const float* __restrict__ dww,
                                          const float* __restrict__ dwb,
                                          const float* __restrict__ scaw,
                                          const float* __restrict__ scab,
                                          const float* __restrict__ pw2w){
  extern __shared__ char sm[];
  uint32_t* ts = (uint32_t*)sm;
  __nv_bfloat16* xs = (__nv_bfloat16*)(sm + TS_WORDS*4);
  float2* wsm = (float2*)(sm + TS_WORDS*4 + 64*72*2);
  float2* bsm = (float2*)(sm + TS_WORDS*4 + 64*72*2 + 64*9*8);

  int wblk=blockIdx.x, hblk=blockIdx.y, n=blockIdx.z, tid=threadIdx.x;
  int h0=hblk*8, w0=wblk*32;
  int wid=tid>>5, lane=tid&31, grp=lane>>2, t4=lane&3, m0=wid*16;

  if(tid<64){
#pragma unroll
    for(int j=0;j<9;j++) wsm[tid*9+j]=make_float2(dww[tid*9+j], dww[(tid+64)*9+j]);
    bsm[tid]=make_float2(dwb[tid], dwb[tid+64]);
  }

  const __nv_bfloat16* wf=g_w1f+(size_t)n*128*64;
  uint32_t A[4][4]; loadA(A,wf,m0,grp,t4);
  int mA=m0+grp, mB=m0+grp+8;
  float bv0=g_b1f[n*128+mA], bv8=g_b1f[n*128+mB];
  __nv_bfloat16* tsh=(__nv_bfloat16*)ts;
  const int iA0=(mA&63)*688+(mA>>6), iB0=(mB&63)*688+(mB>>6);

  const int pl=tid&63, c0=tid>>6;
  const float* xb=x+(size_t)n*64*HW;
  float v[16];
  {
    int p=pl;
    int pr=p/34, pc=p-pr*34;
    int hh=h0-1+pr, wn=w0-1+pc;
    bool ok=((unsigned)hh<256u)&&((unsigned)wn<256u);
    const float* px=xb+(size_t)c0*HW+hh*256+wn;
#pragma unroll
    for(int j=0;j<16;j++) v[j]= ok ? px[(size_t)(4*j)*HW] : 0.f;
  }
  for(int chk=0;chk<6;chk++){
    if(chk) __syncthreads();
#pragma unroll
    for(int j=0;j<16;j++) xs[pl*72+c0+4*j]=__float2bfloat16(v[j]);
    __syncthreads();
    if(chk<5){
      int p=(chk+1)*64+pl;
      int pr=p/34, pc=p-pr*34;
      int hh=h0-1+pr, wn=w0-1+pc;
      bool ok=(p<344)&&((unsigned)hh<256u)&&((unsigned)wn<256u);
      const float* px=xb+(size_t)c0*HW+hh*256+wn;
#pragma unroll
      for(int j=0;j<16;j++) v[j]= ok ? px[(size_t)(4*j)*HW] : 0.f;
    }
    int pbase=chk*64;
#pragma unroll
    for(int g=0;g<8;g++){
      int p0=g*8;
      const __nv_bfloat16* bs=xs+(p0+grp)*72+2*t4;
      float d0=0,d1=0,d2=0,d3=0;
#pragma unroll
      for(int k=0;k<4;k++){
        uint32_t b0=*(const uint32_t*)(bs+k*16), b1=*(const uint32_t*)(bs+k*16+8);
        mma_bf16(d0,d1,d2,d3,A[k][0],A[k][1],A[k][2],A[k][3],b0,b1);
      }
      int px=pbase+p0+2*t4;
      if(px<344){
        bool vA=pvalid(px,h0,w0), vB=pvalid(px+1,h0,w0);
        tsh[iA0+px*2]    =__float2bfloat16(vA?(d0+bv0):0.f);
        tsh[iA0+px*2+2]  =__float2bfloat16(vB?(d1+bv0):0.f);
        tsh[iB0+px*2]    =__float2bfloat16(vA?(d2+bv8):0.f);
        tsh[iB0+px*2+2]  =__float2bfloat16(vB?(d3+bv8):0.f);
      }
    }
  }
  __syncthreads();

  __nv_bfloat16* yb=g_y+(size_t)n*64*HW;
  float psumTot[8];
  for(int j=0;j<8;j++){
    int cp=wid*8+j;
    const uint32_t* tp=ts+cp*344;
    float2 wz[9];
#pragma unroll
    for(int q=0;q<9;q++) wz[q]=wsm[cp*9+q];
    float2 bz=bsm[cp];
    float2 r0[3],r1[3],r2[3];
#pragma unroll
    for(int k=0;k<3;k++){
      r0[k]=__bfloat1622float2(*(const __nv_bfloat162*)&tp[lane+k]);
      r1[k]=__bfloat1622float2(*(const __nv_bfloat162*)&tp[34+lane+k]);
    }
    float psum=0.f;
#pragma unroll
    for(int r=0;r<8;r++){
#pragma unroll
      for(int k=0;k<3;k++)
        r2[k]=__bfloat1622float2(*(const __nv_bfloat162*)&tp[(r+2)*34+lane+k]);
      float ax=bz.x, ay=bz.y;
#pragma unroll
      for(int k=0;k<3;k++){
        ax=fmaf(wz[k].x,  r0[k].x,ax); ay=fmaf(wz[k].y,  r0[k].y,ay);
        ax=fmaf(wz[3+k].x,r1[k].x,ax); ay=fmaf(wz[3+k].y,r1[k].y,ay);
        ax=fmaf(wz[6+k].x,r2[k].x,ax); ay=fmaf(wz[6+k].y,r2[k].y,ay);
      }
      float gv=ax*ay;
      yb[(size_t)cp*HW+(h0+r)*256+w0+lane]=__float2bfloat16(gv);
      psum+=gv;
#pragma unroll
      for(int k=0;k<3;k++){ r0[k]=r1[k]; r1[k]=r2[k]; }
    }
    psumTot[j]=warpsum(psum);
  }
  if(lane==0){
#pragma unroll
    for(int j=0;j<8;j++) atomicAdd(&g_pool[n*64+wid*8+j],psumTot[j]);
    __threadfence();
  }
  __syncthreads();
  __shared__ int last3;
  if(tid==0) last3=(atomicAdd(&g_cnt3[n],1)==255);
  __syncthreads();
  if(!last3) return;
  if(tid==0) g_cnt3[n]=0;
  __shared__ float vsig[64];
  if(tid<64){
    float s=scab[tid];
    for(int c=0;c<64;c++) s+=scaw[tid*64+c]*(g_pool[n*64+c]*(1.f/HW));
    vsig[tid]=1.f/(1.f+expf(-s));
    g_s2[n*64+tid]=0.f; g_q2[n*64+tid]=0.f;
  }
  __syncthreads();
  for(int i=tid;i<4096;i+=256) g_w2f[n*4096+i]=__float2bfloat16(pw2w[i]*vsig[i&63]);
}

// ---------------- K5: pw2 GEMM (128px) + Csm epilogue + residual1 + ln2 stats + fold -----
#define K5_SMEM (128*72*2 + 128*66*4)   // 18432 + 33792 = 52224
__global__ __launch_bounds__(256) void k5(const float* __restrict__ x,
                                          const float* __restrict__ pw2b,
                                          const float* __restrict__ beta1,
                                          float* __restrict__ out,
                                          const float* __restrict__ ln2w,const float* __restrict__ ln2b,
                                          const float* __restrict__ pw3w,const float* __restrict__ pw3b){
  extern __shared__ char sm5[];
  __nv_bfloat16* xs=(__nv_bfloat16*)sm5;              // [128][72]
  float* Csm=(float*)(sm5+18432);                     // [128][66]
  int blk=blockIdx.x, n=blockIdx.y, tid=threadIdx.x;
  int base=blk*128;
  const __nv_bfloat16* yp=g_y+(size_t)n*64*HW+base;
  // staging: bf16x2 loads (2 px) x 4 channels -> 2 STS.64
#pragma unroll
  for(int it=0;it<4;it++){
    int idx=it*256+tid;
    int p2=(idx&63)*2, cg=idx>>6, c0=cg*4;
    __nv_bfloat162 v0=*(const __nv_bfloat162*)&yp[(size_t)c0*HW+p2];
    __nv_bfloat162 v1=*(const __nv_bfloat162*)&yp[(size_t)(c0+1)*HW+p2];
    __nv_bfloat162 v2=*(const __nv_bfloat162*)&yp[(size_t)(c0+2)*HW+p2];
    __nv_bfloat162 v3=*(const __nv_bfloat162*)&yp[(size_t)(c0+3)*HW+p2];
    uint32_t a0=PK2RAW(v0.x,v1.x), b0=PK2RAW(v2.x,v3.x);
    uint32_t a1=PK2RAW(v0.y,v1.y), b1=PK2RAW(v2.y,v3.y);
    *(uint2*)((char*)xs + p2*144 + c0*2)    =make_uint2(a0,b0);
    *(uint2*)((char*)xs + (p2+1)*144 + c0*2)=make_uint2(a1,b1);
  }
  __syncthreads();
  int wid=tid>>5, lane=tid&31, grp=lane>>2, t4=lane&3;
  {
    int m0=(wid&3)*16, ph=(wid>>2)*64;
    const __nv_bfloat16* wf=g_w2f+n*64*64;
    uint32_t A[4][4]; loadA(A,wf,m0,grp,t4);
    for(int nt=0;nt<8;nt++){
      int p0=ph+nt*8;
      const __nv_bfloat16* bs=xs+(p0+grp)*72+2*t4;
      float d0=0,d1=0,d2=0,d3=0;
#pragma unroll
      for(int k=0;k<4;k++){
        uint32_t b0=*(const uint32_t*)(bs+k*16), b1=*(const uint32_t*)(bs+k*16+8);
        mma_bf16(d0,d1,d2,d3,A[k][0],A[k][1],A[k][2],A[k][3],b0,b1);
      }
      int px=p0+2*t4;
      Csm[px*66+m0+grp]      =d0;
      Csm[(px+1)*66+m0+grp]  =d1;
      Csm[px*66+m0+grp+8]    =d2;
      Csm[(px+1)*66+m0+grp+8]=d3;
    }
  }
  __syncthreads();
  // coalesced epilogue + ln2 stats
  {
    int c=8*wid+(lane>>2);
    float be=beta1[c], bi=pw2b[c];
    const float* xr=x+(size_t)(n*64+c)*HW+base;
    float* orow=out+(size_t)(n*64+c)*HW+base;
    float s=0.f,q=0.f;
#pragma unroll
    for(int k=0;k<8;k++){
      int px=(lane&3)*4+16*k;
      float4 xv=*(const float4*)&xr[px];
      float o0=xv.x+be*(Csm[px*66+c]+bi);
      float o1=xv.y+be*(Csm[(px+1)*66+c]+bi);
      float o2=xv.z+be*(Csm[(px+2)*66+c]+bi);
      float o3=xv.w+be*(Csm[(px+3)*66+c]+bi);
      *(float4*)&orow[px]=make_float4(o0,o1,o2,o3);
      s+=(o0+o1)+(o2+o3); q+=o0*o0+o1*o1+o2*o2+o3*o3;
    }
    s+=__shfl_xor_sync(0xffffffffu,s,1); s+=__shfl_xor_sync(0xffffffffu,s,2);
    q+=__shfl_xor_sync(0xffffffffu,q,1); q+=__shfl_xor_sync(0xffffffffu,q,2);
    if((lane&3)==0){ atomicAdd(&g_s2[n*64+c],s); atomicAdd(&g_q2[n*64+c],q); }
  }
  __threadfence();
  __syncthreads();
  // ---- tail: last block per n folds ln2 into pw3 (gate-paired row reorder) ----
  __shared__ int last5;
  if(tid==0) last5=(atomicAdd(&g_cnt5[n],1)==511);
  __syncthreads();
  if(!last5) return;
  if(tid==0) g_cnt5[n]=0;
  __shared__ float a2[64], cc2[64];
  if(tid<64){
    float mean=g_s2[n*64+tid]*(1.f/HW);
    float var =g_q2[n*64+tid]*(1.f/HW)-mean*mean;
    float ai=ln2w[tid]*rsqrtf(var+1e-6f);
    a2[tid]=ai; cc2[tid]=ln2b[tid]-mean*ai;
  }
  __syncthreads();
  if(tid<128){
    int o=tid;
    int ob2=(o<64)?o:(o-64);
    int rr=(ob2>>3)*16 + (ob2&7) + ((o<64)?0:8);
    float bacc=pw3b[o];
#pragma unroll 8
    for(int c=0;c<64;c++){
      float w=pw3w[o*64+c];
      bacc+=w*cc2[c];
      g_w3f[(n*128+rr)*64+c]=__float2bfloat16(w*a2[c]);
    }
    g_b3f[n*128+o]=bacc;
  }
}

// ---------------- K7: pw3 + gate + pw4 + residual2; Csm epilogue ----------------
#define K7_SMEM (128*66*4 + 128*72*2)   // Csm overlays xs; ts after. total 52224
__global__ __launch_bounds__(256) void k7(const float* __restrict__ pw4b,
                                          const float* __restrict__ beta2,
                                          float* __restrict__ out){
  extern __shared__ char sm7[];
  __nv_bfloat16* xs=(__nv_bfloat16*)sm7;              // [128][72], dead after stage1
  __nv_bfloat16* ts=(__nv_bfloat16*)(sm7+33792);      // [128][72] gated acts
  float* Csm=(float*)sm7;                             // [128][66] overlays xs
  int blk=blockIdx.x, n=blockIdx.y, tid=threadIdx.x;
  int base=blk*128;
  const float* xp=out+(size_t)n*64*HW+base;
  {
#pragma unroll
    for(int j=0;j<8;j++){
      int idx=j*256+tid;
      int p=idx&127, cg=idx>>7, c0=cg*4;
      float f0=xp[(size_t)c0*HW+p],     f1=xp[(size_t)(c0+1)*HW+p];
      float f2=xp[(size_t)(c0+2)*HW+p], f3=xp[(size_t)(c0+3)*HW+p];
      uint32_t a=pkf(f0,f1), b=pkf(f2,f3);
      *(uint2*)((char*)xs + p*144 + c0*2)=make_uint2(a,b);
    }
  }
  __syncthreads();
  int wid=tid>>5, lane=tid&31, grp=lane>>2, t4=lane&3;
  { // stage 1: gate-paired W3 rows; each warp: 2 m-tiles (pair groups), 64 px
    int pg0=2*(wid&3);
    int m0=16*pg0;
    int ph=(wid>>2)*64;
    const __nv_bfloat16* wf=g_w3f+(size_t)n*128*64;
    uint32_t A0[4][4], A1[4][4];
    loadA(A0,wf,m0,grp,t4); loadA(A1,wf,m0+16,grp,t4);
    const float* b3=g_b3f+n*128;
    float br0=b3[pg0*8+grp],     bp0=b3[64+pg0*8+grp];
    float br1=b3[(pg0+1)*8+grp], bp1=b3[64+(pg0+1)*8+grp];
    int cc0=pg0*8+grp, cc1=(pg0+1)*8+grp;
    for(int nt=0;nt<8;nt++){
      int p0=ph+nt*8;
      const __nv_bfloat16* bs=xs+(p0+grp)*72+2*t4;
      float d00=br0,d01=br0,d02=bp0,d03=bp0;
      float d10=br1,d11=br1,d12=bp1,d13=bp1;
#pragma unroll
      for(int k=0;k<4;k++){
        uint32_t b0=*(const uint32_t*)(bs+k*16), b1=*(const uint32_t*)(bs+k*16+8);
        mma_bf16(d00,d01,d02,d03,A0[k][0],A0[k][1],A0[k][2],A0[k][3],b0,b1);
        mma_bf16(d10,d11,d12,d13,A1[k][0],A1[k][1],A1[k][2],A1[k][3],b0,b1);
      }
      int px=p0+2*t4;
      ts[px*72+cc0]    =__float2bfloat16(d00*d02);
      ts[(px+1)*72+cc0]=__float2bfloat16(d01*d03);
      ts[px*72+cc1]    =__float2bfloat16(d10*d12);
      ts[(px+1)*72+cc1]=__float2bfloat16(d11*d13);
    }
  }
  __syncthreads();
  { // stage 2: z = W4 @ gated -> Csm (xs region now dead)
    int m0=(wid&3)*16, ph=(wid>>2)*64;
    uint32_t A[4][4]; loadA(A,g_w4h,m0,grp,t4);
    for(int nt=0;nt<8;nt++){
      int p0=ph+nt*8;
      const __nv_bfloat16* bs=ts+(p0+grp)*72+2*t4;
      float d0=0,d1=0,d2=0,d3=0;
#pragma unroll
      for(int k=0;k<4;k++){
        uint32_t b0=*(const uint32_t*)(bs+k*16), b1=*(const uint32_t*)(bs+k*16+8);
        mma_bf16(d0,d1,d2,d3,A[k][0],A[k][1],A[k][2],A[k][3],b0,b1);
      }
      int px=p0+2*t4;
      Csm[px*66+m0+grp]      =d0;
      Csm[(px+1)*66+m0+grp]  =d1;
      Csm[px*66+m0+grp+8]    =d2;
      Csm[(px+1)*66+m0+grp+8]=d3;
    }
  }
  __syncthreads();
  // coalesced epilogue: out += beta2*(C + b4)
  {
    int c=8*wid+(lane>>2);
    float be=beta2[c], bi=pw4b[c];
    float* orow=out+(size_t)(n*64+c)*HW+base;
#pragma unroll
    for(int k=0;k<8;k++){
      int px=(lane&3)*4+16*k;
      float4 r=*(const float4*)&orow[px];
      r.x+=be*(Csm[px*66+c]+bi);
      r.y+=be*(Csm[(px+1)*66+c]+bi);
      r.z+=be*(Csm[(px+2)*66+c]+bi);
      r.w+=be*(Csm[(px+3)*66+c]+bi);
      *(float4*)&orow[px]=r;
    }
  }
}

extern "C" void kernel_launch(void* const* d_in, const int* in_sizes, int n_in,
                              void* d_out, int out_size){
  const float* x    =(const float*)d_in[0];
  const float* ln1w =(const float*)d_in[1];
  const float* ln1b =(const float*)d_in[2];
  const float* pw1w =(const float*)d_in[3];
  const float* pw1b =(const float*)d_in[4];
  const float* dww  =(const float*)d_in[5];
  const float* dwb  =(const float*)d_in[6];
  const float* scaw =(const float*)d_in[7];
  const float* scab =(const float*)d_in[8];
  const float* pw2w =(const float*)d_in[9];
  const float* pw2b =(const float*)d_in[10];
  const float* ln2w =(const float*)d_in[11];
  const float* ln2b =(const float*)d_in[12];
  const float* pw3w =(const float*)d_in[13];
  const float* pw3b =(const float*)d_in[14];
  const float* pw4w =(const float*)d_in[15];
  const float* pw4b =(const float*)d_in[16];
  const float* beta1=(const float*)d_in[17];
  const float* beta2=(const float*)d_in[18];
  float* out=(float*)d_out;

  cudaFuncSetAttribute(k3, cudaFuncAttributeMaxDynamicSharedMemorySize, K3_SMEM);
  cudaFuncSetAttribute(k5, cudaFuncAttributeMaxDynamicSharedMemorySize, K5_SMEM);
  cudaFuncSetAttribute(k7, cudaFuncAttributeMaxDynamicSharedMemorySize, K7_SMEM);

  k1 <<<512,256>>>(x,ln1w,ln1b,pw1w,pw1b,pw4w);
  k3 <<<dim3(8,32,8),256,K3_SMEM>>>(x,dww,dwb,scaw,scab,pw2w);
  k5 <<<dim3(512,8),256,K5_SMEM>>>(x,pw2b,beta1,out,ln2w,ln2b,pw3w,pw3b);
  k7 <<<dim3(512,8),256,K7_SMEM>>>(pw4b,beta2,out);
}

// round 14
// speedup vs baseline: 1.0609x; 1.0609x over previous
#include <cuda_runtime.h>
#include <cuda_bf16.h>
#include <cstdint>

#define HW 65536
#define NB 8

// ---- scratch (__device__ globals; allocation is forbidden) ----
__device__ float g_sum[512], g_sq[512], g_pool[512], g_s2[512], g_q2[512];
__device__ float g_b1f[NB*128], g_b3f[NB*128];
__device__ __nv_bfloat16 g_w1f[NB*128*64], g_w3f[NB*128*64], g_w2f[NB*64*64], g_w4h[64*64];
__device__ __nv_bfloat16 g_y[(size_t)NB*64*HW];    // gate output (64 MB)
__device__ int g_cnt1[NB], g_cnt3[NB], g_cnt5[NB]; // zero-init; self-reset each use

__device__ __forceinline__ float warpsum(float v){
#pragma unroll
  for(int o=16;o>0;o>>=1) v += __shfl_down_sync(0xffffffffu, v, o);
  return v;
}

__device__ __forceinline__ void mma_bf16(float& d0,float& d1,float& d2,float& d3,
    uint32_t a0,uint32_t a1,uint32_t a2,uint32_t a3,uint32_t b0,uint32_t b1){
  asm volatile("mma.sync.aligned.m16n8k16.row.col.f32.bf16.bf16.f32 "
    "{%0,%1,%2,%3},{%4,%5,%6,%7},{%8,%9},{%0,%1,%2,%3};"
    : "+f"(d0),"+f"(d1),"+f"(d2),"+f"(d3)
    : "r"(a0),"r"(a1),"r"(a2),"r"(a3),"r"(b0),"r"(b1));
}

__device__ __forceinline__ uint32_t pkf(float a,float b){
  __nv_bfloat162 p=__floats2bfloat162_rn(a,b);
  return *(uint32_t*)&p;
}
#define PK2RAW(lo,hi) ((uint32_t)(*(const unsigned short*)&(lo)) | ((uint32_t)(*(const unsigned short*)&(hi))<<16))

// load A fragments (4 k-steps) from row-major bf16 [rows][64]
__device__ __forceinline__ void loadA(uint32_t A[4][4], const __nv_bfloat16* wf,
                                      int m0,int grp,int t4){
#pragma unroll
  for(int k=0;k<4;k++){
    int c0=k*16+2*t4;
    A[k][0]=*(const uint32_t*)(wf+(m0+grp)*64+c0);
    A[k][1]=*(const uint32_t*)(wf+(m0+grp+8)*64+c0);
    A[k][2]=*(const uint32_t*)(wf+(m0+grp)*64+c0+8);
    A[k][3]=*(const uint32_t*)(wf+(m0+grp+8)*64+c0+8);
  }
}

// ---------------- K1: stats of x + (last block per n) ln1->pw1 fold ----------------
__global__ __launch_bounds__(256) void k1(const float* __restrict__ x,
                                          const float* __restrict__ ln1w,const float* __restrict__ ln1b,
                                          const float* __restrict__ pw1w,const float* __restrict__ pw1b,
                                          const float* __restrict__ pw4w){
  int nc=blockIdx.x, n=nc>>6, tid=threadIdx.x;
  const float4* p=(const float4*)(x+(size_t)nc*HW);
  float s=0.f,q=0.f;
  for(int i=tid;i<HW/4;i+=256){
    float4 v=p[i];
    s+=(v.x+v.y)+(v.z+v.w);
    q+=v.x*v.x+v.y*v.y+v.z*v.z+v.w*v.w;
  }
  s=warpsum(s); q=warpsum(q);
  __shared__ float rs[8],rq[8];
  if((tid&31)==0){rs[tid>>5]=s;rq[tid>>5]=q;}
  __syncthreads();
  __shared__ int lastf;
  if(tid==0){
    float S=0,Q=0;
#pragma unroll
    for(int i=0;i<8;i++){S+=rs[i];Q+=rq[i];}
    g_sum[nc]=S; g_sq[nc]=Q;
    __threadfence();
    lastf=(atomicAdd(&g_cnt1[n],1)==63);
  }
  __syncthreads();
  if(!lastf) return;
  if(tid==0){ g_cnt1[n]=0; __threadfence(); }
  __shared__ float a[64], cc[64];
  if(tid<64){
    float mean=g_sum[n*64+tid]*(1.f/HW);
    float var =g_sq[n*64+tid]*(1.f/HW)-mean*mean;
    float ai=ln1w[tid]*rsqrtf(var+1e-6f);
    a[tid]=ai; cc[tid]=ln1b[tid]-mean*ai;
    g_pool[n*64+tid]=0.f;
  }
  __syncthreads();
  if(tid<128){
    int o=tid;
    float bacc=pw1b[o];
#pragma unroll 8
    for(int c=0;c<64;c++){
      float w=pw1w[o*64+c];
      bacc+=w*cc[c];
      g_w1f[(n*128+o)*64+c]=__float2bfloat16(w*a[c]);
    }
    g_b1f[n*128+o]=bacc;
  } else if(n==0 && tid<192){
    int o=tid-128;
    for(int c=0;c<64;c++) g_w4h[o*64+c]=__float2bfloat16(pw4w[o*64+c]);
  }
}

// ---------------- K3 (fused): pw1 GEMM + depthwise3x3 + gate + pool + SCA fold ----------------
#define TS_WORDS (64*344)
#define K3_SMEM (TS_WORDS*4 + 64*72*2 + 64*9*8 + 64*8)   // 102400 B

__device__ __forceinline__ bool pvalid(int p,int h0,int w0){
  int pr=p/34, pc=p-pr*34;
  int hh=h0-1+pr, wn=w0-1+pc;
  return ((unsigned)hh<256u)&&((unsigned)wn<256u);
}

__global__ __launch_bounds__(256) void k3(const float* __restrict__ x,
                                          const float* __restrict__ dww,
                                          const float* __restrict__ dwb,
                                          const float* __restrict__ scaw,
                                          const float* __restrict__ scab,
                                          const float* __restrict__ pw2w){
  extern __shared__ char sm[];
  uint32_t* ts = (uint32_t*)sm;
  __nv_bfloat16* xs = (__nv_bfloat16*)(sm + TS_WORDS*4);
  float2* wsm = (float2*)(sm + TS_WORDS*4 + 64*72*2);
  float2* bsm = (float2*)(sm + TS_WORDS*4 + 64*72*2 + 64*9*8);

  int wblk=blockIdx.x, hblk=blockIdx.y, n=blockIdx.z, tid=threadIdx.x;
  int h0=hblk*8, w0=wblk*32;
  int wid=tid>>5, lane=tid&31, grp=lane>>2, t4=lane&3, m0=wid*16;

  if(tid<64){
#pragma unroll
    for(int j=0;j<9;j++) wsm[tid*9+j]=make_float2(dww[tid*9+j], dww[(tid+64)*9+j]);
    bsm[tid]=make_float2(dwb[tid], dwb[tid+64]);
  }

  const __nv_bfloat16* wf=g_w1f+(size_t)n*128*64;
  uint32_t A[4][4]; loadA(A,wf,m0,grp,t4);
  int mA=m0+grp, mB=m0+grp+8;
  float bv0=g_b1f[n*128+mA], bv8=g_b1f[n*128+mB];
  __nv_bfloat16* tsh=(__nv_bfloat16*)ts;
  const int iA0=(mA&63)*688+(mA>>6), iB0=(mB&63)*688+(mB>>6);

  const int pl=tid&63, c0=tid>>6;
  const float* xb=x+(size_t)n*64*HW;
  float v[16];
  {
    int p=pl;
    int pr=p/34, pc=p-pr*34;
    int hh=h0-1+pr, wn=w0-1+pc;
    bool ok=((unsigned)hh<256u)&&((unsigned)wn<256u);
    const float* px=xb+(size_t)c0*HW+hh*256+wn;
#pragma unroll
    for(int j=0;j<16;j++) v[j]= ok ? px[(size_t)(4*j)*HW] : 0.f;
  }
  for(int chk=0;chk<6;chk++){
    if(chk) __syncthreads();
#pragma unroll
    for(int j=0;j<16;j++) xs[pl*72+c0+4*j]=__float2bfloat16(v[j]);
    __syncthreads();
    if(chk<5){
      int p=(chk+1)*64+pl;
      int pr=p/34, pc=p-pr*34;
      int hh=h0-1+pr, wn=w0-1+pc;
      bool ok=(p<344)&&((unsigned)hh<256u)&&((unsigned)wn<256u);
      const float* px=xb+(size_t)c0*HW+hh*256+wn;
#pragma unroll
      for(int j=0;j<16;j++) v[j]= ok ? px[(size_t)(4*j)*HW] : 0.f;
    }
    int pbase=chk*64;
#pragma unroll
    for(int g=0;g<8;g++){
      int p0=g*8;
      const __nv_bfloat16* bs=xs+(p0+grp)*72+2*t4;
      float d0=0,d1=0,d2=0,d3=0;
#pragma unroll
      for(int k=0;k<4;k++){
        uint32_t b0=*(const uint32_t*)(bs+k*16), b1=*(const uint32_t*)(bs+k*16+8);
        mma_bf16(d0,d1,d2,d3,A[k][0],A[k][1],A[k][2],A[k][3],b0,b1);
      }
      int px=pbase+p0+2*t4;
      if(px<344){
        bool vA=pvalid(px,h0,w0), vB=pvalid(px+1,h0,w0);
        tsh[iA0+px*2]    =__float2bfloat16(vA?(d0+bv0):0.f);
        tsh[iA0+px*2+2]  =__float2bfloat16(vB?(d1+bv0):0.f);
        tsh[iB0+px*2]    =__float2bfloat16(vA?(d2+bv8):0.f);
        tsh[iB0+px*2+2]  =__float2bfloat16(vB?(d3+bv8):0.f);
      }
    }
  }
  __syncthreads();

  __nv_bfloat16* yb=g_y+(size_t)n*64*HW;
  float psumTot[8];
  for(int j=0;j<8;j++){
    int cp=wid*8+j;
    const uint32_t* tp=ts+cp*344;
    float2 wz[9];
#pragma unroll
    for(int q=0;q<9;q++) wz[q]=wsm[cp*9+q];
    float2 bz=bsm[cp];
    float2 r0[3],r1[3],r2[3];
#pragma unroll
    for(int k=0;k<3;k++){
      r0[k]=__bfloat1622float2(*(const __nv_bfloat162*)&tp[lane+k]);
      r1[k]=__bfloat1622float2(*(const __nv_bfloat162*)&tp[34+lane+k]);
    }
    float psum=0.f;
#pragma unroll
    for(int r=0;r<8;r++){
#pragma unroll
      for(int k=0;k<3;k++)
        r2[k]=__bfloat1622float2(*(const __nv_bfloat162*)&tp[(r+2)*34+lane+k]);
      float ax=bz.x, ay=bz.y;
#pragma unroll
      for(int k=0;k<3;k++){
        ax=fmaf(wz[k].x,  r0[k].x,ax); ay=fmaf(wz[k].y,  r0[k].y,ay);
        ax=fmaf(wz[3+k].x,r1[k].x,ax); ay=fmaf(wz[3+k].y,r1[k].y,ay);
        ax=fmaf(wz[6+k].x,r2[k].x,ax); ay=fmaf(wz[6+k].y,r2[k].y,ay);
      }
      float gv=ax*ay;
      yb[(size_t)cp*HW+(h0+r)*256+w0+lane]=__float2bfloat16(gv);
      psum+=gv;
#pragma unroll
      for(int k=0;k<3;k++){ r0[k]=r1[k]; r1[k]=r2[k]; }
    }
    psumTot[j]=warpsum(psum);
  }
  if(lane==0){
#pragma unroll
    for(int j=0;j<8;j++) atomicAdd(&g_pool[n*64+wid*8+j],psumTot[j]);
    __threadfence();
  }
  __syncthreads();
  __shared__ int last3;
  if(tid==0) last3=(atomicAdd(&g_cnt3[n],1)==255);
  __syncthreads();
  if(!last3) return;
  if(tid==0) g_cnt3[n]=0;
  __shared__ float vsig[64];
  if(tid<64){
    float s=scab[tid];
    for(int c=0;c<64;c++) s+=scaw[tid*64+c]*(g_pool[n*64+c]*(1.f/HW));
    vsig[tid]=1.f/(1.f+expf(-s));
    g_s2[n*64+tid]=0.f; g_q2[n*64+tid]=0.f;
  }
  __syncthreads();
  for(int i=tid;i<4096;i+=256) g_w2f[n*4096+i]=__float2bfloat16(pw2w[i]*vsig[i&63]);
}

// ---------------- K5: pw2 GEMM (2 m-tiles/warp) + residual1 + ln2 stats + fold ----------------
__global__ __launch_bounds__(256) void k5(const float* __restrict__ x,
                                          const float* __restrict__ pw2b,
                                          const float* __restrict__ beta1,
                                          float* __restrict__ out,
                                          const float* __restrict__ ln2w,const float* __restrict__ ln2b,
                                          const float* __restrict__ pw3w,const float* __restrict__ pw3b){
  int row=blockIdx.x, n=blockIdx.y, tid=threadIdx.x;
  __shared__ __nv_bfloat16 xs[256*72];
  __shared__ float ss[64], sq[64];
  if(tid<64){ss[tid]=0.f;sq[tid]=0.f;}
  const __nv_bfloat16* yp=g_y+(size_t)n*64*HW+row*256;
  // staging: bf16x2 loads (2 px) x 4 channels -> 2 STS.64 (128B/wavefront)
  // 256 px x 64 ch / (2px*4ch per iter) / 256 threads = 8 iterations
#pragma unroll
  for(int it=0;it<8;it++){
    int idx=it*256+tid;
    int p2=(idx&127)*2, cg=idx>>7, c0=cg*4;
    __nv_bfloat162 v0=*(const __nv_bfloat162*)&yp[(size_t)c0*HW+p2];
    __nv_bfloat162 v1=*(const __nv_bfloat162*)&yp[(size_t)(c0+1)*HW+p2];
    __nv_bfloat162 v2=*(const __nv_bfloat162*)&yp[(size_t)(c0+2)*HW+p2];
    __nv_bfloat162 v3=*(const __nv_bfloat162*)&yp[(size_t)(c0+3)*HW+p2];
    uint32_t a0=PK2RAW(v0.x,v1.x), b0=PK2RAW(v2.x,v3.x);
    uint32_t a1=PK2RAW(v0.y,v1.y), b1=PK2RAW(v2.y,v3.y);
    *(uint2*)((char*)xs + p2*144 + c0*2)    =make_uint2(a0,b0);
    *(uint2*)((char*)xs + (p2+1)*144 + c0*2)=make_uint2(a1,b1);
  }
  __syncthreads();
  int wid=tid>>5, lane=tid&31, grp=lane>>2, t4=lane&3;
  int m0=(wid&1)*32, ph=(wid>>1)*64;
  const __nv_bfloat16* wf=g_w2f+n*64*64;
  uint32_t A0[4][4], A1[4][4];
  loadA(A0,wf,m0,grp,t4); loadA(A1,wf,m0+16,grp,t4);
  int c0A=m0+grp, c0B=m0+grp+8, c1A=m0+16+grp, c1B=m0+24+grp;
  float bi0A=pw2b[c0A],bi0B=pw2b[c0B],bi1A=pw2b[c1A],bi1B=pw2b[c1B];
  float be0A=beta1[c0A],be0B=beta1[c0B],be1A=beta1[c1A],be1B=beta1[c1B];
  const float* xb=x+(size_t)n*64*HW+row*256;
  float* ob=out+(size_t)n*64*HW+row*256;
  float s0A=0,q0A=0,s0B=0,q0B=0,s1A=0,q1A=0,s1B=0,q1B=0;
  for(int nt=0;nt<8;nt++){
    int p0=ph+nt*8;
    const __nv_bfloat16* bs=xs+(p0+grp)*72+2*t4;
    float d00=0,d01=0,d02=0,d03=0, d10=0,d11=0,d12=0,d13=0;
#pragma unroll
    for(int k=0;k<4;k++){
      uint32_t b0=*(const uint32_t*)(bs+k*16), b1=*(const uint32_t*)(bs+k*16+8);
      mma_bf16(d00,d01,d02,d03,A0[k][0],A0[k][1],A0[k][2],A0[k][3],b0,b1);
      mma_bf16(d10,d11,d12,d13,A1[k][0],A1[k][1],A1[k][2],A1[k][3],b0,b1);
    }
    int px=p0+2*t4;
    {
      float2 xa=*(const float2*)(xb+(size_t)c0A*HW+px), xc=*(const float2*)(xb+(size_t)c0B*HW+px);
      float o0=xa.x+be0A*(d00+bi0A), o1=xa.y+be0A*(d01+bi0A);
      float o2=xc.x+be0B*(d02+bi0B), o3=xc.y+be0B*(d03+bi0B);
      *(float2*)(ob+(size_t)c0A*HW+px)=make_float2(o0,o1);
      *(float2*)(ob+(size_t)c0B*HW+px)=make_float2(o2,o3);
      s0A+=o0+o1; q0A+=o0*o0+o1*o1; s0B+=o2+o3; q0B+=o2*o2+o3*o3;
    }
    {
      float2 xa=*(const float2*)(xb+(size_t)c1A*HW+px), xc=*(const float2*)(xb+(size_t)c1B*HW+px);
      float o0=xa.x+be1A*(d10+bi1A), o1=xa.y+be1A*(d11+bi1A);
      float o2=xc.x+be1B*(d12+bi1B), o3=xc.y+be1B*(d13+bi1B);
      *(float2*)(ob+(size_t)c1A*HW+px)=make_float2(o0,o1);
      *(float2*)(ob+(size_t)c1B*HW+px)=make_float2(o2,o3);
      s1A+=o0+o1; q1A+=o0*o0+o1*o1; s1B+=o2+o3; q1B+=o2*o2+o3*o3;
    }
  }
#pragma unroll
  for(int off=2;off>0;off>>=1){
    s0A+=__shfl_down_sync(0xffffffffu,s0A,off); q0A+=__shfl_down_sync(0xffffffffu,q0A,off);
    s0B+=__shfl_down_sync(0xffffffffu,s0B,off); q0B+=__shfl_down_sync(0xffffffffu,q0B,off);
    s1A+=__shfl_down_sync(0xffffffffu,s1A,off); q1A+=__shfl_down_sync(0xffffffffu,q1A,off);
    s1B+=__shfl_down_sync(0xffffffffu,s1B,off); q1B+=__shfl_down_sync(0xffffffffu,q1B,off);
  }
  if(t4==0){
    atomicAdd(&ss[c0A],s0A); atomicAdd(&sq[c0A],q0A);
    atomicAdd(&ss[c0B],s0B); atomicAdd(&sq[c0B],q0B);
    atomicAdd(&ss[c1A],s1A); atomicAdd(&sq[c1A],q1A);
    atomicAdd(&ss[c1B],s1B); atomicAdd(&sq[c1B],q1B);
  }
  __syncthreads();
  if(tid<64){
    atomicAdd(&g_s2[n*64+tid],ss[tid]); atomicAdd(&g_q2[n*64+tid],sq[tid]);
    __threadfence();
  }
  __syncthreads();
  __shared__ int last5;
  if(tid==0) last5=(atomicAdd(&g_cnt5[n],1)==255);
  __syncthreads();
  if(!last5) return;
  if(tid==0) g_cnt5[n]=0;
  __shared__ float a2[64], cc2[64];
  if(tid<64){
    float mean=g_s2[n*64+tid]*(1.f/HW);
    float var =g_q2[n*64+tid]*(1.f/HW)-mean*mean;
    float ai=ln2w[tid]*rsqrtf(var+1e-6f);
    a2[tid]=ai; cc2[tid]=ln2b[tid]-mean*ai;
  }
  __syncthreads();
  if(tid<128){
    int o=tid;
    // channel-interleaved gate-paired reorder:
    // tile pg = c&7, row r = c>>3 (raw) / +8 (partner); rr = pg*16 + r (+8)
    int c=o&63, po=o>>6;
    int rr=(c&7)*16 + (c>>3) + po*8;
    float bacc=pw3b[o];
#pragma unroll 8
    for(int cc=0;cc<64;cc++){
      float w=pw3w[o*64+cc];
      bacc+=w*cc2[cc];
      g_w3f[(n*128+rr)*64+cc]=__float2bfloat16(w*a2[cc]);
    }
    g_b3f[n*128+o]=bacc;
  }
}

// ---------------- K7: pw3 + gate + pw4 + residual2; 256px/CTA, packed gate stores --------
#define K7_SMEM (256*72*2*2)   // xs 36864 + ts 36864 = 73728
__global__ __launch_bounds__(256) void k7(const float* __restrict__ pw4b,
                                          const float* __restrict__ beta2,
                                          float* __restrict__ out){
  extern __shared__ char sm7[];
  __nv_bfloat16* xs=(__nv_bfloat16*)sm7;            // [256][72]
  __nv_bfloat16* ts=(__nv_bfloat16*)(sm7+36864);    // [256][72] gated acts
  int blk=blockIdx.x, n=blockIdx.y, tid=threadIdx.x;
  int base=blk*256;
  const float* xp=out+(size_t)n*64*HW+base;
  {
#pragma unroll
    for(int j=0;j<16;j++){
      int idx=j*256+tid;
      int p=idx&255, cg=idx>>8, c0=cg*4;
      float f0=xp[(size_t)c0*HW+p],     f1=xp[(size_t)(c0+1)*HW+p];
      float f2=xp[(size_t)(c0+2)*HW+p], f3=xp[(size_t)(c0+3)*HW+p];
      uint32_t a=pkf(f0,f1), b=pkf(f2,f3);
      *(uint2*)((char*)xs + p*144 + c0*2)=make_uint2(a,b);
    }
  }
  __syncthreads();
  int wid=tid>>5, lane=tid&31, grp=lane>>2, t4=lane&3;
  { // stage 1: interleaved gate-paired W3 rows; warp: 2 pair-group m-tiles, 128 px
    int pg0=2*(wid&3);
    int m0=16*pg0;
    int ph=(wid>>2)*128;
    const __nv_bfloat16* wf=g_w3f+(size_t)n*128*64;
    uint32_t A0[4][4], A1[4][4];
    loadA(A0,wf,m0,grp,t4); loadA(A1,wf,m0+16,grp,t4);
    const float* b3=g_b3f+n*128;
    // chain0: raw ch cc0 = pg0 + 8*grp; chain1: cc1 = cc0+1
    int cc0=pg0+8*grp;
    float br0=b3[cc0],   bp0=b3[64+cc0];
    float br1=b3[cc0+1], bp1=b3[64+cc0+1];
    for(int nt=0;nt<16;nt++){
      int p0=ph+nt*8;
      const __nv_bfloat16* bs=xs+(p0+grp)*72+2*t4;
      float d00=br0,d01=br0,d02=bp0,d03=bp0;
      float d10=br1,d11=br1,d12=bp1,d13=bp1;
#pragma unroll
      for(int k=0;k<4;k++){
        uint32_t b0=*(const uint32_t*)(bs+k*16), b1=*(const uint32_t*)(bs+k*16+8);
        mma_bf16(d00,d01,d02,d03,A0[k][0],A0[k][1],A0[k][2],A0[k][3],b0,b1);
        mma_bf16(d10,d11,d12,d13,A1[k][0],A1[k][1],A1[k][2],A1[k][3],b0,b1);
      }
      int px=p0+2*t4;
      // packed STS.32: channels cc0, cc0+1 for each pixel
      *(uint32_t*)&ts[px*72+cc0]    =pkf(d00*d02, d10*d12);
      *(uint32_t*)&ts[(px+1)*72+cc0]=pkf(d01*d03, d11*d13);
    }
  }
  __syncthreads();
  { // stage 2: z = W4 @ gated; out += beta2*(z+b4)
    int m0=(wid&3)*16, ph=(wid>>2)*128;
    uint32_t A[4][4]; loadA(A,g_w4h,m0,grp,t4);
    int cA=m0+grp, cB=m0+grp+8;
    float biA=pw4b[cA],biB=pw4b[cB],beA=beta2[cA],beB=beta2[cB];
    float* opA=out+(size_t)(n*64+cA)*HW+base;
    float* opB=out+(size_t)(n*64+cB)*HW+base;
    for(int nt=0;nt<16;nt++){
      int p0=ph+nt*8;
      const __nv_bfloat16* bs=ts+(p0+grp)*72+2*t4;
      float d0=0,d1=0,d2=0,d3=0;
#pragma unroll
      for(int k=0;k<4;k++){
        uint32_t b0=*(const uint32_t*)(bs+k*16), b1=*(const uint32_t*)(bs+k*16+8);
        mma_bf16(d0,d1,d2,d3,A[k][0],A[k][1],A[k][2],A[k][3],b0,b1);
      }
      int px=p0+2*t4;
      float2 xa=*(const float2*)(opA+px), xb=*(const float2*)(opB+px);
      float o0=xa.x+beA*(d0+biA), o1=xa.y+beA*(d1+biA);
      float o2=xb.x+beB*(d2+biB), o3=xb.y+beB*(d3+biB);
      *(float2*)(opA+px)=make_float2(o0,o1);
      *(float2*)(opB+px)=make_float2(o2,o3);
    }
  }
}

extern "C" void kernel_launch(void* const* d_in, const int* in_sizes, int n_in,
                              void* d_out, int out_size){
  const float* x    =(const float*)d_in[0];
  const float* ln1w =(const float*)d_in[1];
  const float* ln1b =(const float*)d_in[2];
  const float* pw1w =(const float*)d_in[3];
  const float* pw1b =(const float*)d_in[4];
  const float* dww  =(const float*)d_in[5];
  const float* dwb  =(const float*)d_in[6];
  const float* scaw =(const float*)d_in[7];
  const float* scab =(const float*)d_in[8];
  const float* pw2w =(const float*)d_in[9];
  const float* pw2b =(const float*)d_in[10];
  const float* ln2w =(const float*)d_in[11];
  const float* ln2b =(const float*)d_in[12];
  const float* pw3w =(const float*)d_in[13];
  const float* pw3b =(const float*)d_in[14];
  const float* pw4w =(const float*)d_in[15];
  const float* pw4b =(const float*)d_in[16];
  const float* beta1=(const float*)d_in[17];
  const float* beta2=(const float*)d_in[18];
  float* out=(float*)d_out;

  cudaFuncSetAttribute(k3, cudaFuncAttributeMaxDynamicSharedMemorySize, K3_SMEM);
  cudaFuncSetAttribute(k7, cudaFuncAttributeMaxDynamicSharedMemorySize, K7_SMEM);

  k1 <<<512,256>>>(x,ln1w,ln1b,pw1w,pw1b,pw4w);
  k3 <<<dim3(8,32,8),256,K3_SMEM>>>(x,dww,dwb,scaw,scab,pw2w);
  k5 <<<dim3(256,8),256>>>(x,pw2b,beta1,out,ln2w,ln2b,pw3w,pw3b);
  k7 <<<dim3(256,8),256,K7_SMEM>>>(pw4b,beta2,out);   // 256 px/CTA -> 256 blocks
}

// round 15
// speedup vs baseline: 1.1149x; 1.0509x over previous
#include <cuda_runtime.h>
#include <cuda_bf16.h>
#include <cstdint>

#define HW 65536
#define NB 8

// ---- scratch (__device__ globals; allocation is forbidden) ----
__device__ float g_sum[512], g_sq[512], g_pool[512], g_s2[512], g_q2[512];
__device__ float g_b1f[NB*128], g_b3f[NB*128];
__device__ __nv_bfloat16 g_w1f[NB*128*64], g_w3f[NB*128*64], g_w2f[NB*64*64], g_w4h[64*64];
__device__ __nv_bfloat16 g_y[(size_t)NB*64*HW];    // gate output (64 MB)
__device__ int g_cnt1[NB], g_cnt3[NB], g_cnt5[NB]; // zero-init; self-reset each use

__device__ __forceinline__ float warpsum(float v){
#pragma unroll
  for(int o=16;o>0;o>>=1) v += __shfl_down_sync(0xffffffffu, v, o);
  return v;
}

__device__ __forceinline__ void mma_bf16(float& d0,float& d1,float& d2,float& d3,
    uint32_t a0,uint32_t a1,uint32_t a2,uint32_t a3,uint32_t b0,uint32_t b1){
  asm volatile("mma.sync.aligned.m16n8k16.row.col.f32.bf16.bf16.f32 "
    "{%0,%1,%2,%3},{%4,%5,%6,%7},{%8,%9},{%0,%1,%2,%3};"
    : "+f"(d0),"+f"(d1),"+f"(d2),"+f"(d3)
    : "r"(a0),"r"(a1),"r"(a2),"r"(a3),"r"(b0),"r"(b1));
}

__device__ __forceinline__ uint32_t pkf(float a,float b){
  __nv_bfloat162 p=__floats2bfloat162_rn(a,b);
  return *(uint32_t*)&p;
}
#define PK2RAW(lo,hi) ((uint32_t)(*(const unsigned short*)&(lo)) | ((uint32_t)(*(const unsigned short*)&(hi))<<16))

// load A fragments (4 k-steps) from row-major bf16 [rows][64]
__device__ __forceinline__ void loadA(uint32_t A[4][4], const __nv_bfloat16* wf,
                                      int m0,int grp,int t4){
#pragma unroll
  for(int k=0;k<4;k++){
    int c0=k*16+2*t4;
    A[k][0]=*(const uint32_t*)(wf+(m0+grp)*64+c0);
    A[k][1]=*(const uint32_t*)(wf+(m0+grp+8)*64+c0);
    A[k][2]=*(const uint32_t*)(wf+(m0+grp)*64+c0+8);
    A[k][3]=*(const uint32_t*)(wf+(m0+grp+8)*64+c0+8);
  }
}

// ---------------- K1: stats of x + (last block per n) ln1->pw1 fold ----------------
// NOTE: g_w1f rows are written GATE-PAIR REORDERED: raw channel c -> row (c>>3)*16+(c&7),
// partner channel 64+c -> row (c>>3)*16+(c&7)+8. g_b1f stays in original channel order.
__global__ __launch_bounds__(256) void k1(const float* __restrict__ x,
                                          const float* __restrict__ ln1w,const float* __restrict__ ln1b,
                                          const float* __restrict__ pw1w,const float* __restrict__ pw1b,
                                          const float* __restrict__ pw4w){
  int nc=blockIdx.x, n=nc>>6, tid=threadIdx.x;
  const float4* p=(const float4*)(x+(size_t)nc*HW);
  float s=0.f,q=0.f;
  for(int i=tid;i<HW/4;i+=256){
    float4 v=p[i];
    s+=(v.x+v.y)+(v.z+v.w);
    q+=v.x*v.x+v.y*v.y+v.z*v.z+v.w*v.w;
  }
  s=warpsum(s); q=warpsum(q);
  __shared__ float rs[8],rq[8];
  if((tid&31)==0){rs[tid>>5]=s;rq[tid>>5]=q;}
  __syncthreads();
  __shared__ int lastf;
  if(tid==0){
    float S=0,Q=0;
#pragma unroll
    for(int i=0;i<8;i++){S+=rs[i];Q+=rq[i];}
    g_sum[nc]=S; g_sq[nc]=Q;
    __threadfence();
    lastf=(atomicAdd(&g_cnt1[n],1)==63);
  }
  __syncthreads();
  if(!lastf) return;
  if(tid==0){ g_cnt1[n]=0; __threadfence(); }
  __shared__ float a[64], cc[64];
  if(tid<64){
    float mean=g_sum[n*64+tid]*(1.f/HW);
    float var =g_sq[n*64+tid]*(1.f/HW)-mean*mean;
    float ai=ln1w[tid]*rsqrtf(var+1e-6f);
    a[tid]=ai; cc[tid]=ln1b[tid]-mean*ai;
    g_pool[n*64+tid]=0.f;
  }
  __syncthreads();
  if(tid<128){
    int o=tid;
    int ob2=(o<64)?o:(o-64);
    int rr=(ob2>>3)*16 + (ob2&7) + ((o<64)?0:8);   // gate-pair reorder
    float bacc=pw1b[o];
#pragma unroll 8
    for(int c=0;c<64;c++){
      float w=pw1w[o*64+c];
      bacc+=w*cc[c];
      g_w1f[(n*128+rr)*64+c]=__float2bfloat16(w*a[c]);
    }
    g_b1f[n*128+o]=bacc;
  } else if(n==0 && tid<192){
    int o=tid-128;
    for(int c=0;c<64;c++) g_w4h[o*64+c]=__float2bfloat16(pw4w[o*64+c]);
  }
}

// ---------------- K3 (fused): pw1 GEMM + depthwise3x3 + gate + pool + SCA fold ----------------
#define TS_WORDS (64*344)
#define K3_SMEM (TS_WORDS*4 + 64*72*2 + 64*9*8 + 64*8)   // 102400 B

__device__ __forceinline__ bool pvalid(int p,int h0,int w0){
  int pr=p/34, pc=p-pr*34;
  int hh=h0-1+pr, wn=w0-1+pc;
  return ((unsigned)hh<256u)&&((unsigned)wn<256u);
}

__global__ __launch_bounds__(256) void k3(const float* __restrict__ x,
                                          const float* __restrict__ dww,
                                          const float* __restrict__ dwb,
                                          const float* __restrict__ scaw,
                                          const float* __restrict__ scab,
                                          const float* __restrict__ pw2w){
  extern __shared__ char sm[];
  uint32_t* ts = (uint32_t*)sm;                       // [64 cp][344 px] word=(c, c+64)
  __nv_bfloat16* xs = (__nv_bfloat16*)(sm + TS_WORDS*4);
  float2* wsm = (float2*)(sm + TS_WORDS*4 + 64*72*2);
  float2* bsm = (float2*)(sm + TS_WORDS*4 + 64*72*2 + 64*9*8);

  int wblk=blockIdx.x, hblk=blockIdx.y, n=blockIdx.z, tid=threadIdx.x;
  int h0=hblk*8, w0=wblk*32;
  int wid=tid>>5, lane=tid&31, grp=lane>>2, t4=lane&3;

  if(tid<64){
#pragma unroll
    for(int j=0;j<9;j++) wsm[tid*9+j]=make_float2(dww[tid*9+j], dww[(tid+64)*9+j]);
    bsm[tid]=make_float2(dwb[tid], dwb[tid+64]);
  }

  // warp-tiled phase1: warp owns pair-groups pg0, pg0+1 and half the chunk pixels
  const int pg0=2*(wid&3);
  const int ph=(wid>>2)*32;
  const __nv_bfloat16* wf=g_w1f+(size_t)n*128*64;
  uint32_t A0[4][4], A1[4][4];
  loadA(A0,wf,16*pg0,grp,t4); loadA(A1,wf,16*pg0+16,grp,t4);
  const int ch0=pg0*8+grp, ch1=ch0+8;
  const float bc0=g_b1f[n*128+ch0], bp0=g_b1f[n*128+64+ch0];
  const float bc1=g_b1f[n*128+ch1], bp1=g_b1f[n*128+64+ch1];

  const int pl=tid&63, c0=tid>>6;
  const float* xb=x+(size_t)n*64*HW;
  float v[16];
  {
    int p=pl;
    int pr=p/34, pc=p-pr*34;
    int hh=h0-1+pr, wn=w0-1+pc;
    bool ok=((unsigned)hh<256u)&&((unsigned)wn<256u);
    const float* px=xb+(size_t)c0*HW+hh*256+wn;
#pragma unroll
    for(int j=0;j<16;j++) v[j]= ok ? px[(size_t)(4*j)*HW] : 0.f;
  }
  for(int chk=0;chk<6;chk++){
    if(chk) __syncthreads();
#pragma unroll
    for(int j=0;j<16;j++) xs[pl*72+c0+4*j]=__float2bfloat16(v[j]);
    __syncthreads();
    if(chk<5){
      int p=(chk+1)*64+pl;
      int pr=p/34, pc=p-pr*34;
      int hh=h0-1+pr, wn=w0-1+pc;
      bool ok=(p<344)&&((unsigned)hh<256u)&&((unsigned)wn<256u);
      const float* px=xb+(size_t)c0*HW+hh*256+wn;
#pragma unroll
      for(int j=0;j<16;j++) v[j]= ok ? px[(size_t)(4*j)*HW] : 0.f;
    }
    int pbase=chk*64;
#pragma unroll
    for(int g2=0;g2<4;g2++){
      int p0=ph+g2*8;
      const __nv_bfloat16* bs=xs+(p0+grp)*72+2*t4;
      float d00=0,d01=0,d02=0,d03=0, d10=0,d11=0,d12=0,d13=0;
#pragma unroll
      for(int k=0;k<4;k++){
        uint32_t b0=*(const uint32_t*)(bs+k*16), b1=*(const uint32_t*)(bs+k*16+8);
        mma_bf16(d00,d01,d02,d03,A0[k][0],A0[k][1],A0[k][2],A0[k][3],b0,b1);
        mma_bf16(d10,d11,d12,d13,A1[k][0],A1[k][1],A1[k][2],A1[k][3],b0,b1);
      }
      int px=pbase+p0+2*t4;
      if(px<344){
        bool vA=pvalid(px,h0,w0), vB=pvalid(px+1,h0,w0);
        ts[ch0*344+px]  = vA ? pkf(d00+bc0, d02+bp0) : 0u;
        ts[ch0*344+px+1]= vB ? pkf(d01+bc0, d03+bp0) : 0u;
        ts[ch1*344+px]  = vA ? pkf(d10+bc1, d12+bp1) : 0u;
        ts[ch1*344+px+1]= vB ? pkf(d11+bc1, d13+bp1) : 0u;
      }
    }
  }
  __syncthreads();

  __nv_bfloat16* yb=g_y+(size_t)n*64*HW;
  float psumTot[8];
  for(int j=0;j<8;j++){
    int cp=wid*8+j;
    const uint32_t* tp=ts+cp*344;
    float2 wz[9];
#pragma unroll
    for(int q=0;q<9;q++) wz[q]=wsm[cp*9+q];
    float2 bz=bsm[cp];
    float2 r0[3],r1[3],r2[3];
#pragma unroll
    for(int k=0;k<3;k++){
      r0[k]=__bfloat1622float2(*(const __nv_bfloat162*)&tp[lane+k]);
      r1[k]=__bfloat1622float2(*(const __nv_bfloat162*)&tp[34+lane+k]);
    }
    float psum=0.f;
#pragma unroll
    for(int r=0;r<8;r++){
#pragma unroll
      for(int k=0;k<3;k++)
        r2[k]=__bfloat1622float2(*(const __nv_bfloat162*)&tp[(r+2)*34+lane+k]);
      float ax=bz.x, ay=bz.y;
#pragma unroll
      for(int k=0;k<3;k++){
        ax=fmaf(wz[k].x,  r0[k].x,ax); ay=fmaf(wz[k].y,  r0[k].y,ay);
        ax=fmaf(wz[3+k].x,r1[k].x,ax); ay=fmaf(wz[3+k].y,r1[k].y,ay);
        ax=fmaf(wz[6+k].x,r2[k].x,ax); ay=fmaf(wz[6+k].y,r2[k].y,ay);
      }
      float gv=ax*ay;
      yb[(size_t)cp*HW+(h0+r)*256+w0+lane]=__float2bfloat16(gv);
      psum+=gv;
#pragma unroll
      for(int k=0;k<3;k++){ r0[k]=r1[k]; r1[k]=r2[k]; }
    }
    psumTot[j]=warpsum(psum);
  }
  if(lane==0){
#pragma unroll
    for(int j=0;j<8;j++) atomicAdd(&g_pool[n*64+wid*8+j],psumTot[j]);
    __threadfence();
  }
  __syncthreads();
  __shared__ int last3;
  if(tid==0) last3=(atomicAdd(&g_cnt3[n],1)==255);
  __syncthreads();
  if(!last3) return;
  if(tid==0) g_cnt3[n]=0;
  __shared__ float vsig[64];
  if(tid<64){
    float s=scab[tid];
    for(int c=0;c<64;c++) s+=scaw[tid*64+c]*(g_pool[n*64+c]*(1.f/HW));
    vsig[tid]=1.f/(1.f+expf(-s));
    g_s2[n*64+tid]=0.f; g_q2[n*64+tid]=0.f;
  }
  __syncthreads();
  for(int i=tid;i<4096;i+=256) g_w2f[n*4096+i]=__float2bfloat16(pw2w[i]*vsig[i&63]);
}

// ---------------- K5: pw2 GEMM (2 m-tiles/warp) + residual1 + ln2 stats + fold ----------------
__global__ __launch_bounds__(256) void k5(const float* __restrict__ x,
                                          const float* __restrict__ pw2b,
                                          const float* __restrict__ beta1,
                                          float* __restrict__ out,
                                          const float* __restrict__ ln2w,const float* __restrict__ ln2b,
                                          const float* __restrict__ pw3w,const float* __restrict__ pw3b){
  int row=blockIdx.x, n=blockIdx.y, tid=threadIdx.x;
  __shared__ __nv_bfloat16 xs[256*72];
  __shared__ float ss[64], sq[64];
  if(tid<64){ss[tid]=0.f;sq[tid]=0.f;}
  const __nv_bfloat16* yp=g_y+(size_t)n*64*HW+row*256;
#pragma unroll
  for(int it=0;it<8;it++){
    int idx=it*256+tid;
    int p2=(idx&127)*2, cg=idx>>7, c0=cg*4;
    __nv_bfloat162 v0=*(const __nv_bfloat162*)&yp[(size_t)c0*HW+p2];
    __nv_bfloat162 v1=*(const __nv_bfloat162*)&yp[(size_t)(c0+1)*HW+p2];
    __nv_bfloat162 v2=*(const __nv_bfloat162*)&yp[(size_t)(c0+2)*HW+p2];
    __nv_bfloat162 v3=*(const __nv_bfloat162*)&yp[(size_t)(c0+3)*HW+p2];
    uint32_t a0=PK2RAW(v0.x,v1.x), b0=PK2RAW(v2.x,v3.x);
    uint32_t a1=PK2RAW(v0.y,v1.y), b1=PK2RAW(v2.y,v3.y);
    *(uint2*)((char*)xs + p2*144 + c0*2)    =make_uint2(a0,b0);
    *(uint2*)((char*)xs + (p2+1)*144 + c0*2)=make_uint2(a1,b1);
  }
  __syncthreads();
  int wid=tid>>5, lane=tid&31, grp=lane>>2, t4=lane&3;
  int m0=(wid&1)*32, ph=(wid>>1)*64;
  const __nv_bfloat16* wf=g_w2f+n*64*64;
  uint32_t A0[4][4], A1[4][4];
  loadA(A0,wf,m0,grp,t4); loadA(A1,wf,m0+16,grp,t4);
  int c0A=m0+grp, c0B=m0+grp+8, c1A=m0+16+grp, c1B=m0+24+grp;
  float bi0A=pw2b[c0A],bi0B=pw2b[c0B],bi1A=pw2b[c1A],bi1B=pw2b[c1B];
  float be0A=beta1[c0A],be0B=beta1[c0B],be1A=beta1[c1A],be1B=beta1[c1B];
  const float* xb=x+(size_t)n*64*HW+row*256;
  float* ob=out+(size_t)n*64*HW+row*256;
  float s0A=0,q0A=0,s0B=0,q0B=0,s1A=0,q1A=0,s1B=0,q1B=0;
  for(int nt=0;nt<8;nt++){
    int p0=ph+nt*8;
    const __nv_bfloat16* bs=xs+(p0+grp)*72+2*t4;
    float d00=0,d01=0,d02=0,d03=0, d10=0,d11=0,d12=0,d13=0;
#pragma unroll
    for(int k=0;k<4;k++){
      uint32_t b0=*(const uint32_t*)(bs+k*16), b1=*(const uint32_t*)(bs+k*16+8);
      mma_bf16(d00,d01,d02,d03,A0[k][0],A0[k][1],A0[k][2],A0[k][3],b0,b1);
      mma_bf16(d10,d11,d12,d13,A1[k][0],A1[k][1],A1[k][2],A1[k][3],b0,b1);
    }
    int px=p0+2*t4;
    {
      float2 xa=*(const float2*)(xb+(size_t)c0A*HW+px), xc=*(const float2*)(xb+(size_t)c0B*HW+px);
      float o0=xa.x+be0A*(d00+bi0A), o1=xa.y+be0A*(d01+bi0A);
      float o2=xc.x+be0B*(d02+bi0B), o3=xc.y+be0B*(d03+bi0B);
      *(float2*)(ob+(size_t)c0A*HW+px)=make_float2(o0,o1);
      *(float2*)(ob+(size_t)c0B*HW+px)=make_float2(o2,o3);
      s0A+=o0+o1; q0A+=o0*o0+o1*o1; s0B+=o2+o3; q0B+=o2*o2+o3*o3;
    }
    {
      float2 xa=*(const float2*)(xb+(size_t)c1A*HW+px), xc=*(const float2*)(xb+(size_t)c1B*HW+px);
      float o0=xa.x+be1A*(d10+bi1A), o1=xa.y+be1A*(d11+bi1A);
      float o2=xc.x+be1B*(d12+bi1B), o3=xc.y+be1B*(d13+bi1B);
      *(float2*)(ob+(size_t)c1A*HW+px)=make_float2(o0,o1);
      *(float2*)(ob+(size_t)c1B*HW+px)=make_float2(o2,o3);
      s1A+=o0+o1; q1A+=o0*o0+o1*o1; s1B+=o2+o3; q1B+=o2*o2+o3*o3;
    }
  }
#pragma unroll
  for(int off=2;off>0;off>>=1){
    s0A+=__shfl_down_sync(0xffffffffu,s0A,off); q0A+=__shfl_down_sync(0xffffffffu,q0A,off);
    s0B+=__shfl_down_sync(0xffffffffu,s0B,off); q0B+=__shfl_down_sync(0xffffffffu,q0B,off);
    s1A+=__shfl_down_sync(0xffffffffu,s1A,off); q1A+=__shfl_down_sync(0xffffffffu,q1A,off);
    s1B+=__shfl_down_sync(0xffffffffu,s1B,off); q1B+=__shfl_down_sync(0xffffffffu,q1B,off);
  }
  if(t4==0){
    atomicAdd(&ss[c0A],s0A); atomicAdd(&sq[c0A],q0A);
    atomicAdd(&ss[c0B],s0B); atomicAdd(&sq[c0B],q0B);
    atomicAdd(&ss[c1A],s1A); atomicAdd(&sq[c1A],q1A);
    atomicAdd(&ss[c1B],s1B); atomicAdd(&sq[c1B],q1B);
  }
  __syncthreads();
  if(tid<64){
    atomicAdd(&g_s2[n*64+tid],ss[tid]); atomicAdd(&g_q2[n*64+tid],sq[tid]);
    __threadfence();
  }
  __syncthreads();
  __shared__ int last5;
  if(tid==0) last5=(atomicAdd(&g_cnt5[n],1)==255);
  __syncthreads();
  if(!last5) return;
  if(tid==0) g_cnt5[n]=0;
  __shared__ float a2[64], cc2[64];
  if(tid<64){
    float mean=g_s2[n*64+tid]*(1.f/HW);
    float var =g_q2[n*64+tid]*(1.f/HW)-mean*mean;
    float ai=ln2w[tid]*rsqrtf(var+1e-6f);
    a2[tid]=ai; cc2[tid]=ln2b[tid]-mean*ai;
  }
  __syncthreads();
  if(tid<128){
    int o=tid;
    // channel-interleaved gate-paired reorder for k7 stage1
    int c=o&63, po=o>>6;
    int rr=(c&7)*16 + (c>>3) + po*8;
    float bacc=pw3b[o];
#pragma unroll 8
    for(int cc=0;cc<64;cc++){
      float w=pw3w[o*64+cc];
      bacc+=w*cc2[cc];
      g_w3f[(n*128+rr)*64+cc]=__float2bfloat16(w*a2[cc]);
    }
    g_b3f[n*128+o]=bacc;
  }
}

// ---------------- K7: pw3 + gate + pw4 + residual2; 256px/CTA, packed gate stores --------
#define K7_SMEM (256*72*2*2)   // xs 36864 + ts 36864 = 73728
__global__ __launch_bounds__(256) void k7(const float* __restrict__ pw4b,
                                          const float* __restrict__ beta2,
                                          float* __restrict__ out){
  extern __shared__ char sm7[];
  __nv_bfloat16* xs=(__nv_bfloat16*)sm7;            // [256][72]
  __nv_bfloat16* ts=(__nv_bfloat16*)(sm7+36864);    // [256][72] gated acts
  int blk=blockIdx.x, n=blockIdx.y, tid=threadIdx.x;
  int base=blk*256;
  const float* xp=out+(size_t)n*64*HW+base;
  {
#pragma unroll
    for(int j=0;j<16;j++){
      int idx=j*256+tid;
      int p=idx&255, cg=idx>>8, c0=cg*4;
      float f0=xp[(size_t)c0*HW+p],     f1=xp[(size_t)(c0+1)*HW+p];
      float f2=xp[(size_t)(c0+2)*HW+p], f3=xp[(size_t)(c0+3)*HW+p];
      uint32_t a=pkf(f0,f1), b=pkf(f2,f3);
      *(uint2*)((char*)xs + p*144 + c0*2)=make_uint2(a,b);
    }
  }
  __syncthreads();
  int wid=tid>>5, lane=tid&31, grp=lane>>2, t4=lane&3;
  { // stage 1: interleaved gate-paired W3 rows; warp: 2 pair-group m-tiles, 128 px
    int pg0=2*(wid&3);
    int m0=16*pg0;
    int ph=(wid>>2)*128;
    const __nv_bfloat16* wf=g_w3f+(size_t)n*128*64;
    uint32_t A0[4][4], A1[4][4];
    loadA(A0,wf,m0,grp,t4); loadA(A1,wf,m0+16,grp,t4);
    const float* b3=g_b3f+n*128;
    int cc0=pg0+8*grp;
    float br0=b3[cc0],   bp0=b3[64+cc0];
    float br1=b3[cc0+1], bp1=b3[64+cc0+1];
    for(int nt=0;nt<16;nt++){
      int p0=ph+nt*8;
      const __nv_bfloat16* bs=xs+(p0+grp)*72+2*t4;
      float d00=br0,d01=br0,d02=bp0,d03=bp0;
      float d10=br1,d11=br1,d12=bp1,d13=bp1;
#pragma unroll
      for(int k=0;k<4;k++){
        uint32_t b0=*(const uint32_t*)(bs+k*16), b1=*(const uint32_t*)(bs+k*16+8);
        mma_bf16(d00,d01,d02,d03,A0[k][0],A0[k][1],A0[k][2],A0[k][3],b0,b1);
        mma_bf16(d10,d11,d12,d13,A1[k][0],A1[k][1],A1[k][2],A1[k][3],b0,b1);
      }
      int px=p0+2*t4;
      *(uint32_t*)&ts[px*72+cc0]    =pkf(d00*d02, d10*d12);
      *(uint32_t*)&ts[(px+1)*72+cc0]=pkf(d01*d03, d11*d13);
    }
  }
  __syncthreads();
  { // stage 2: z = W4 @ gated; out += beta2*(z+b4)
    int m0=(wid&3)*16, ph=(wid>>2)*128;
    uint32_t A[4][4]; loadA(A,g_w4h,m0,grp,t4);
    int cA=m0+grp, cB=m0+grp+8;
    float biA=pw4b[cA],biB=pw4b[cB],beA=beta2[cA],beB=beta2[cB];
    float* opA=out+(size_t)(n*64+cA)*HW+base;
    float* opB=out+(size_t)(n*64+cB)*HW+base;
    for(int nt=0;nt<16;nt++){
      int p0=ph+nt*8;
      const __nv_bfloat16* bs=ts+(p0+grp)*72+2*t4;
      float d0=0,d1=0,d2=0,d3=0;
#pragma unroll
      for(int k=0;k<4;k++){
        uint32_t b0=*(const uint32_t*)(bs+k*16), b1=*(const uint32_t*)(bs+k*16+8);
        mma_bf16(d0,d1,d2,d3,A[k][0],A[k][1],A[k][2],A[k][3],b0,b1);
      }
      int px=p0+2*t4;
      float2 xa=*(const float2*)(opA+px), xb=*(const float2*)(opB+px);
      float o0=xa.x+beA*(d0+biA), o1=xa.y+beA*(d1+biA);
      float o2=xb.x+beB*(d2+biB), o3=xb.y+beB*(d3+biB);
      *(float2*)(opA+px)=make_float2(o0,o1);
      *(float2*)(opB+px)=make_float2(o2,o3);
    }
  }
}

extern "C" void kernel_launch(void* const* d_in, const int* in_sizes, int n_in,
                              void* d_out, int out_size){
  const float* x    =(const float*)d_in[0];
  const float* ln1w =(const float*)d_in[1];
  const float* ln1b =(const float*)d_in[2];
  const float* pw1w =(const float*)d_in[3];
  const float* pw1b =(const float*)d_in[4];
  const float* dww  =(const float*)d_in[5];
  const float* dwb  =(const float*)d_in[6];
  const float* scaw =(const float*)d_in[7];
  const float* scab =(const float*)d_in[8];
  const float* pw2w =(const float*)d_in[9];
  const float* pw2b =(const float*)d_in[10];
  const float* ln2w =(const float*)d_in[11];
  const float* ln2b =(const float*)d_in[12];
  const float* pw3w =(const float*)d_in[13];
  const float* pw3b =(const float*)d_in[14];
  const float* pw4w =(const float*)d_in[15];
  const float* pw4b =(const float*)d_in[16];
  const float* beta1=(const float*)d_in[17];
  const float* beta2=(const float*)d_in[18];
  float* out=(float*)d_out;

  cudaFuncSetAttribute(k3, cudaFuncAttributeMaxDynamicSharedMemorySize, K3_SMEM);
  cudaFuncSetAttribute(k7, cudaFuncAttributeMaxDynamicSharedMemorySize, K7_SMEM);

  k1 <<<512,256>>>(x,ln1w,ln1b,pw1w,pw1b,pw4w);
  k3 <<<dim3(8,32,8),256,K3_SMEM>>>(x,dww,dwb,scaw,scab,pw2w);
  k5 <<<dim3(256,8),256>>>(x,pw2b,beta1,out,ln2w,ln2b,pw3w,pw3b);
  k7 <<<dim3(256,8),256,K7_SMEM>>>(pw4b,beta2,out);
}

// round 16
// speedup vs baseline: 1.1414x; 1.0238x over previous
#include <cuda_runtime.h>
#include <cuda_bf16.h>
#include <cstdint>

#define HW 65536
#define NB 8

// ---- scratch (__device__ globals; allocation is forbidden) ----
__device__ float g_sum[512], g_sq[512], g_pool[512], g_s2[512], g_q2[512];
__device__ float g_b1f[NB*128], g_b3f[NB*128];
__device__ __nv_bfloat16 g_w1f[NB*128*64], g_w3f[NB*128*64], g_w2f[NB*64*64], g_w4h[64*64];
__device__ __nv_bfloat16 g_y[(size_t)NB*64*HW];    // gate output (64 MB)
__device__ int g_cnt1[NB], g_cnt3[NB], g_cnt5[NB]; // zero-init; self-reset each use

__device__ __forceinline__ float warpsum(float v){
#pragma unroll
  for(int o=16;o>0;o>>=1) v += __shfl_down_sync(0xffffffffu, v, o);
  return v;
}

__device__ __forceinline__ void mma_bf16(float& d0,float& d1,float& d2,float& d3,
    uint32_t a0,uint32_t a1,uint32_t a2,uint32_t a3,uint32_t b0,uint32_t b1){
  asm volatile("mma.sync.aligned.m16n8k16.row.col.f32.bf16.bf16.f32 "
    "{%0,%1,%2,%3},{%4,%5,%6,%7},{%8,%9},{%0,%1,%2,%3};"
    : "+f"(d0),"+f"(d1),"+f"(d2),"+f"(d3)
    : "r"(a0),"r"(a1),"r"(a2),"r"(a3),"r"(b0),"r"(b1));
}

__device__ __forceinline__ uint32_t pkf(float a,float b){
  __nv_bfloat162 p=__floats2bfloat162_rn(a,b);
  return *(uint32_t*)&p;
}
#define PK2RAW(lo,hi) ((uint32_t)(*(const unsigned short*)&(lo)) | ((uint32_t)(*(const unsigned short*)&(hi))<<16))

// load A fragments (4 k-steps) from row-major bf16 [rows][64]
__device__ __forceinline__ void loadA(uint32_t A[4][4], const __nv_bfloat16* wf,
                                      int m0,int grp,int t4){
#pragma unroll
  for(int k=0;k<4;k++){
    int c0=k*16+2*t4;
    A[k][0]=*(const uint32_t*)(wf+(m0+grp)*64+c0);
    A[k][1]=*(const uint32_t*)(wf+(m0+grp+8)*64+c0);
    A[k][2]=*(const uint32_t*)(wf+(m0+grp)*64+c0+8);
    A[k][3]=*(const uint32_t*)(wf+(m0+grp+8)*64+c0+8);
  }
}

// ---------------- K1: stats of x + (last block per n) ln1->pw1 fold ----------------
// NOTE: g_w1f rows are written GATE-PAIR REORDERED: raw channel c -> row (c>>3)*16+(c&7),
// partner channel 64+c -> row (c>>3)*16+(c&7)+8. g_b1f stays in original channel order.
__global__ __launch_bounds__(256) void k1(const float* __restrict__ x,
                                          const float* __restrict__ ln1w,const float* __restrict__ ln1b,
                                          const float* __restrict__ pw1w,const float* __restrict__ pw1b,
                                          const float* __restrict__ pw4w){
  int nc=blockIdx.x, n=nc>>6, tid=threadIdx.x;
  const float4* p=(const float4*)(x+(size_t)nc*HW);
  float s=0.f,q=0.f;
  for(int i=tid;i<HW/4;i+=256){
    float4 v=p[i];
    s+=(v.x+v.y)+(v.z+v.w);
    q+=v.x*v.x+v.y*v.y+v.z*v.z+v.w*v.w;
  }
  s=warpsum(s); q=warpsum(q);
  __shared__ float rs[8],rq[8];
  if((tid&31)==0){rs[tid>>5]=s;rq[tid>>5]=q;}
  __syncthreads();
  __shared__ int lastf;
  if(tid==0){
    float S=0,Q=0;
#pragma unroll
    for(int i=0;i<8;i++){S+=rs[i];Q+=rq[i];}
    g_sum[nc]=S; g_sq[nc]=Q;
    __threadfence();
    lastf=(atomicAdd(&g_cnt1[n],1)==63);
  }
  __syncthreads();
  if(!lastf) return;
  if(tid==0){ g_cnt1[n]=0; __threadfence(); }
  __shared__ float a[64], cc[64];
  if(tid<64){
    float mean=g_sum[n*64+tid]*(1.f/HW);
    float var =g_sq[n*64+tid]*(1.f/HW)-mean*mean;
    float ai=ln1w[tid]*rsqrtf(var+1e-6f);
    a[tid]=ai; cc[tid]=ln1b[tid]-mean*ai;
    g_pool[n*64+tid]=0.f;
  }
  __syncthreads();
  if(tid<128){
    int o=tid;
    int ob2=(o<64)?o:(o-64);
    int rr=(ob2>>3)*16 + (ob2&7) + ((o<64)?0:8);   // gate-pair reorder
    float bacc=pw1b[o];
#pragma unroll 8
    for(int c=0;c<64;c++){
      float w=pw1w[o*64+c];
      bacc+=w*cc[c];
      g_w1f[(n*128+rr)*64+c]=__float2bfloat16(w*a[c]);
    }
    g_b1f[n*128+o]=bacc;
  } else if(n==0 && tid<192){
    int o=tid-128;
    for(int c=0;c<64;c++) g_w4h[o*64+c]=__float2bfloat16(pw4w[o*64+c]);
  }
}

// ---------------- K3 (fused): pw1 GEMM + depthwise3x3 + gate + pool + SCA fold ----------------
#define TS_WORDS (64*344)
#define K3_SMEM (TS_WORDS*4 + 64*72*2 + 64*9*8 + 64*8)   // 102400 B

__device__ __forceinline__ bool pvalid(int p,int h0,int w0){
  int pr=p/34, pc=p-pr*34;
  int hh=h0-1+pr, wn=w0-1+pc;
  return ((unsigned)hh<256u)&&((unsigned)wn<256u);
}

__global__ __launch_bounds__(256) void k3(const float* __restrict__ x,
                                          const float* __restrict__ dww,
                                          const float* __restrict__ dwb,
                                          const float* __restrict__ scaw,
                                          const float* __restrict__ scab,
                                          const float* __restrict__ pw2w){
  extern __shared__ char sm[];
  uint32_t* ts = (uint32_t*)sm;                       // [64 cp][344 px] word=(c, c+64)
  __nv_bfloat16* xs = (__nv_bfloat16*)(sm + TS_WORDS*4);
  float2* wsm = (float2*)(sm + TS_WORDS*4 + 64*72*2);
  float2* bsm = (float2*)(sm + TS_WORDS*4 + 64*72*2 + 64*9*8);

  int wblk=blockIdx.x, hblk=blockIdx.y, n=blockIdx.z, tid=threadIdx.x;
  int h0=hblk*8, w0=wblk*32;
  int wid=tid>>5, lane=tid&31, grp=lane>>2, t4=lane&3;

  if(tid<64){
#pragma unroll
    for(int j=0;j<9;j++) wsm[tid*9+j]=make_float2(dww[tid*9+j], dww[(tid+64)*9+j]);
    bsm[tid]=make_float2(dwb[tid], dwb[tid+64]);
  }

  // warp-tiled phase1: warp owns pair-groups pg0, pg0+1 and half the chunk pixels
  const int pg0=2*(wid&3);
  const int ph=(wid>>2)*32;
  const __nv_bfloat16* wf=g_w1f+(size_t)n*128*64;
  uint32_t A0[4][4], A1[4][4];
  loadA(A0,wf,16*pg0,grp,t4); loadA(A1,wf,16*pg0+16,grp,t4);
  const int ch0=pg0*8+grp, ch1=ch0+8;
  const float bc0=g_b1f[n*128+ch0], bp0=g_b1f[n*128+64+ch0];
  const float bc1=g_b1f[n*128+ch1], bp1=g_b1f[n*128+64+ch1];

  // staging assignment: thread owns pixel pl and 16 CONSECUTIVE channels cb..cb+15
  const int pl=tid&63, cb=(tid>>6)*16;
  const float* xb=x+(size_t)n*64*HW;
  float v[16];
  {
    int p=pl;
    int pr=p/34, pc=p-pr*34;
    int hh=h0-1+pr, wn=w0-1+pc;
    bool ok=((unsigned)hh<256u)&&((unsigned)wn<256u);
    const float* px=xb+(size_t)cb*HW+hh*256+wn;
#pragma unroll
    for(int j=0;j<16;j++) v[j]= ok ? px[(size_t)j*HW] : 0.f;
  }
  for(int chk=0;chk<6;chk++){
    if(chk) __syncthreads();
    // packed stores: 4x STS.64, channels contiguous
#pragma unroll
    for(int j=0;j<4;j++){
      uint32_t a=pkf(v[4*j],v[4*j+1]), b=pkf(v[4*j+2],v[4*j+3]);
      *(uint2*)((char*)xs + pl*144 + cb*2 + j*8)=make_uint2(a,b);
    }
    __syncthreads();
    if(chk<5){
      int p=(chk+1)*64+pl;
      int pr=p/34, pc=p-pr*34;
      int hh=h0-1+pr, wn=w0-1+pc;
      bool ok=(p<344)&&((unsigned)hh<256u)&&((unsigned)wn<256u);
      const float* px=xb+(size_t)cb*HW+hh*256+wn;
#pragma unroll
      for(int j=0;j<16;j++) v[j]= ok ? px[(size_t)j*HW] : 0.f;
    }
    int pbase=chk*64;
#pragma unroll
    for(int g2=0;g2<4;g2++){
      int p0=ph+g2*8;
      const __nv_bfloat16* bs=xs+(p0+grp)*72+2*t4;
      float d00=0,d01=0,d02=0,d03=0, d10=0,d11=0,d12=0,d13=0;
#pragma unroll
      for(int k=0;k<4;k++){
        uint32_t b0=*(const uint32_t*)(bs+k*16), b1=*(const uint32_t*)(bs+k*16+8);
        mma_bf16(d00,d01,d02,d03,A0[k][0],A0[k][1],A0[k][2],A0[k][3],b0,b1);
        mma_bf16(d10,d11,d12,d13,A1[k][0],A1[k][1],A1[k][2],A1[k][3],b0,b1);
      }
      int px=pbase+p0+2*t4;
      if(px<344){
        bool vA=pvalid(px,h0,w0), vB=pvalid(px+1,h0,w0);
        ts[ch0*344+px]  = vA ? pkf(d00+bc0, d02+bp0) : 0u;
        ts[ch0*344+px+1]= vB ? pkf(d01+bc0, d03+bp0) : 0u;
        ts[ch1*344+px]  = vA ? pkf(d10+bc1, d12+bp1) : 0u;
        ts[ch1*344+px+1]= vB ? pkf(d11+bc1, d13+bp1) : 0u;
      }
    }
  }
  __syncthreads();

  __nv_bfloat16* yb=g_y+(size_t)n*64*HW;
  float psumTot[8];
  for(int j=0;j<8;j++){
    int cp=wid*8+j;
    const uint32_t* tp=ts+cp*344;
    float2 wz[9];
#pragma unroll
    for(int q=0;q<9;q++) wz[q]=wsm[cp*9+q];
    float2 bz=bsm[cp];
    float2 r0[3],r1[3],r2[3];
#pragma unroll
    for(int k=0;k<3;k++){
      r0[k]=__bfloat1622float2(*(const __nv_bfloat162*)&tp[lane+k]);
      r1[k]=__bfloat1622float2(*(const __nv_bfloat162*)&tp[34+lane+k]);
    }
    float psum=0.f;
#pragma unroll
    for(int r=0;r<8;r++){
#pragma unroll
      for(int k=0;k<3;k++)
        r2[k]=__bfloat1622float2(*(const __nv_bfloat162*)&tp[(r+2)*34+lane+k]);
      float ax=bz.x, ay=bz.y;
#pragma unroll
      for(int k=0;k<3;k++){
        ax=fmaf(wz[k].x,  r0[k].x,ax); ay=fmaf(wz[k].y,  r0[k].y,ay);
        ax=fmaf(wz[3+k].x,r1[k].x,ax); ay=fmaf(wz[3+k].y,r1[k].y,ay);
        ax=fmaf(wz[6+k].x,r2[k].x,ax); ay=fmaf(wz[6+k].y,r2[k].y,ay);
      }
      float gv=ax*ay;
      yb[(size_t)cp*HW+(h0+r)*256+w0+lane]=__float2bfloat16(gv);
      psum+=gv;
#pragma unroll
      for(int k=0;k<3;k++){ r0[k]=r1[k]; r1[k]=r2[k]; }
    }
    psumTot[j]=warpsum(psum);
  }
  if(lane==0){
#pragma unroll
    for(int j=0;j<8;j++) atomicAdd(&g_pool[n*64+wid*8+j],psumTot[j]);
    __threadfence();
  }
  __syncthreads();
  __shared__ int last3;
  if(tid==0) last3=(atomicAdd(&g_cnt3[n],1)==255);
  __syncthreads();
  if(!last3) return;
  if(tid==0) g_cnt3[n]=0;
  __shared__ float vsig[64];
  if(tid<64){
    float s=scab[tid];
    for(int c=0;c<64;c++) s+=scaw[tid*64+c]*(g_pool[n*64+c]*(1.f/HW));
    vsig[tid]=1.f/(1.f+expf(-s));
    g_s2[n*64+tid]=0.f; g_q2[n*64+tid]=0.f;
  }
  __syncthreads();
  for(int i=tid;i<4096;i+=256) g_w2f[n*4096+i]=__float2bfloat16(pw2w[i]*vsig[i&63]);
}

// ---------------- K5: pw2 GEMM (2 m-tiles/warp) + residual1 + ln2 stats + fold ----------------
__global__ __launch_bounds__(256) void k5(const float* __restrict__ x,
                                          const float* __restrict__ pw2b,
                                          const float* __restrict__ beta1,
                                          float* __restrict__ out,
                                          const float* __restrict__ ln2w,const float* __restrict__ ln2b,
                                          const float* __restrict__ pw3w,const float* __restrict__ pw3b){
  int row=blockIdx.x, n=blockIdx.y, tid=threadIdx.x;
  __shared__ __nv_bfloat16 xs[256*72];
  __shared__ float ss[64], sq[64];
  if(tid<64){ss[tid]=0.f;sq[tid]=0.f;}
  const __nv_bfloat16* yp=g_y+(size_t)n*64*HW+row*256;
#pragma unroll
  for(int it=0;it<8;it++){
    int idx=it*256+tid;
    int p2=(idx&127)*2, cg=idx>>7, c0=cg*4;
    __nv_bfloat162 v0=*(const __nv_bfloat162*)&yp[(size_t)c0*HW+p2];
    __nv_bfloat162 v1=*(const __nv_bfloat162*)&yp[(size_t)(c0+1)*HW+p2];
    __nv_bfloat162 v2=*(const __nv_bfloat162*)&yp[(size_t)(c0+2)*HW+p2];
    __nv_bfloat162 v3=*(const __nv_bfloat162*)&yp[(size_t)(c0+3)*HW+p2];
    uint32_t a0=PK2RAW(v0.x,v1.x), b0=PK2RAW(v2.x,v3.x);
    uint32_t a1=PK2RAW(v0.y,v1.y), b1=PK2RAW(v2.y,v3.y);
    *(uint2*)((char*)xs + p2*144 + c0*2)    =make_uint2(a0,b0);
    *(uint2*)((char*)xs + (p2+1)*144 + c0*2)=make_uint2(a1,b1);
  }
  __syncthreads();
  int wid=tid>>5, lane=tid&31, grp=lane>>2, t4=lane&3;
  int m0=(wid&1)*32, ph=(wid>>1)*64;
  const __nv_bfloat16* wf=g_w2f+n*64*64;
  uint32_t A0[4][4], A1[4][4];
  loadA(A0,wf,m0,grp,t4); loadA(A1,wf,m0+16,grp,t4);
  int c0A=m0+grp, c0B=m0+grp+8, c1A=m0+16+grp, c1B=m0+24+grp;
  float bi0A=pw2b[c0A],bi0B=pw2b[c0B],bi1A=pw2b[c1A],bi1B=pw2b[c1B];
  float be0A=beta1[c0A],be0B=beta1[c0B],be1A=beta1[c1A],be1B=beta1[c1B];
  const float* xb=x+(size_t)n*64*HW+row*256;
  float* ob=out+(size_t)n*64*HW+row*256;
  float s0A=0,q0A=0,s0B=0,q0B=0,s1A=0,q1A=0,s1B=0,q1B=0;
  for(int nt=0;nt<8;nt++){
    int p0=ph+nt*8;
    const __nv_bfloat16* bs=xs+(p0+grp)*72+2*t4;
    float d00=0,d01=0,d02=0,d03=0, d10=0,d11=0,d12=0,d13=0;
#pragma unroll
    for(int k=0;k<4;k++){
      uint32_t b0=*(const uint32_t*)(bs+k*16), b1=*(const uint32_t*)(bs+k*16+8);
      mma_bf16(d00,d01,d02,d03,A0[k][0],A0[k][1],A0[k][2],A0[k][3],b0,b1);
      mma_bf16(d10,d11,d12,d13,A1[k][0],A1[k][1],A1[k][2],A1[k][3],b0,b1);
    }
    int px=p0+2*t4;
    {
      float2 xa=*(const float2*)(xb+(size_t)c0A*HW+px), xc=*(const float2*)(xb+(size_t)c0B*HW+px);
      float o0=xa.x+be0A*(d00+bi0A), o1=xa.y+be0A*(d01+bi0A);
      float o2=xc.x+be0B*(d02+bi0B), o3=xc.y+be0B*(d03+bi0B);
      *(float2*)(ob+(size_t)c0A*HW+px)=make_float2(o0,o1);
      *(float2*)(ob+(size_t)c0B*HW+px)=make_float2(o2,o3);
      s0A+=o0+o1; q0A+=o0*o0+o1*o1; s0B+=o2+o3; q0B+=o2*o2+o3*o3;
    }
    {
      float2 xa=*(const float2*)(xb+(size_t)c1A*HW+px), xc=*(const float2*)(xb+(size_t)c1B*HW+px);
      float o0=xa.x+be1A*(d10+bi1A), o1=xa.y+be1A*(d11+bi1A);
      float o2=xc.x+be1B*(d12+bi1B), o3=xc.y+be1B*(d13+bi1B);
      *(float2*)(ob+(size_t)c1A*HW+px)=make_float2(o0,o1);
      *(float2*)(ob+(size_t)c1B*HW+px)=make_float2(o2,o3);
      s1A+=o0+o1; q1A+=o0*o0+o1*o1; s1B+=o2+o3; q1B+=o2*o2+o3*o3;
    }
  }
#pragma unroll
  for(int off=2;off>0;off>>=1){
    s0A+=__shfl_down_sync(0xffffffffu,s0A,off); q0A+=__shfl_down_sync(0xffffffffu,q0A,off);
    s0B+=__shfl_down_sync(0xffffffffu,s0B,off); q0B+=__shfl_down_sync(0xffffffffu,q0B,off);
    s1A+=__shfl_down_sync(0xffffffffu,s1A,off); q1A+=__shfl_down_sync(0xffffffffu,q1A,off);
    s1B+=__shfl_down_sync(0xffffffffu,s1B,off); q1B+=__shfl_down_sync(0xffffffffu,q1B,off);
  }
  if(t4==0){
    atomicAdd(&ss[c0A],s0A); atomicAdd(&sq[c0A],q0A);
    atomicAdd(&ss[c0B],s0B); atomicAdd(&sq[c0B],q0B);
    atomicAdd(&ss[c1A],s1A); atomicAdd(&sq[c1A],q1A);
    atomicAdd(&ss[c1B],s1B); atomicAdd(&sq[c1B],q1B);
  }
  __syncthreads();
  if(tid<64){
    atomicAdd(&g_s2[n*64+tid],ss[tid]); atomicAdd(&g_q2[n*64+tid],sq[tid]);
    __threadfence();
  }
  __syncthreads();
  __shared__ int last5;
  if(tid==0) last5=(atomicAdd(&g_cnt5[n],1)==255);
  __syncthreads();
  if(!last5) return;
  if(tid==0) g_cnt5[n]=0;
  __shared__ float a2[64], cc2[64];
  if(tid<64){
    float mean=g_s2[n*64+tid]*(1.f/HW);
    float var =g_q2[n*64+tid]*(1.f/HW)-mean*mean;
    float ai=ln2w[tid]*rsqrtf(var+1e-6f);
    a2[tid]=ai; cc2[tid]=ln2b[tid]-mean*ai;
  }
  __syncthreads();
  if(tid<128){
    int o=tid;
    // channel-interleaved gate-paired reorder for k7 stage1
    int c=o&63, po=o>>6;
    int rr=(c&7)*16 + (c>>3) + po*8;
    float bacc=pw3b[o];
#pragma unroll 8
    for(int cc=0;cc<64;cc++){
      float w=pw3w[o*64+cc];
      bacc+=w*cc2[cc];
      g_w3f[(n*128+rr)*64+cc]=__float2bfloat16(w*a2[cc]);
    }
    g_b3f[n*128+o]=bacc;
  }
}

// ---------------- K7: pw3 + gate + pw4 + residual2; 256px/CTA, packed gate stores --------
#define K7_SMEM (256*72*2*2)   // xs 36864 + ts 36864 = 73728
__global__ __launch_bounds__(256) void k7(const float* __restrict__ pw4b,
                                          const float* __restrict__ beta2,
                                          float* __restrict__ out){
  extern __shared__ char sm7[];
  __nv_bfloat16* xs=(__nv_bfloat16*)sm7;            // [256][72]
  __nv_bfloat16* ts=(__nv_bfloat16*)(sm7+36864);    // [256][72] gated acts
  int blk=blockIdx.x, n=blockIdx.y, tid=threadIdx.x;
  int base=blk*256;
  const float* xp=out+(size_t)n*64*HW+base;
  {
#pragma unroll
    for(int j=0;j<16;j++){
      int idx=j*256+tid;
      int p=idx&255, cg=idx>>8, c0=cg*4;
      float f0=xp[(size_t)c0*HW+p],     f1=xp[(size_t)(c0+1)*HW+p];
      float f2=xp[(size_t)(c0+2)*HW+p], f3=xp[(size_t)(c0+3)*HW+p];
      uint32_t a=pkf(f0,f1), b=pkf(f2,f3);
      *(uint2*)((char*)xs + p*144 + c0*2)=make_uint2(a,b);
    }
  }
  __syncthreads();
  int wid=tid>>5, lane=tid&31, grp=lane>>2, t4=lane&3;
  { // stage 1: interleaved gate-paired W3 rows; warp: 2 pair-group m-tiles, 128 px
    int pg0=2*(wid&3);
    int m0=16*pg0;
    int ph=(wid>>2)*128;
    const __nv_bfloat16* wf=g_w3f+(size_t)n*128*64;
    uint32_t A0[4][4], A1[4][4];
    loadA(A0,wf,m0,grp,t4); loadA(A1,wf,m0+16,grp,t4);
    const float* b3=g_b3f+n*128;
    int cc0=pg0+8*grp;
    float br0=b3[cc0],   bp0=b3[64+cc0];
    float br1=b3[cc0+1], bp1=b3[64+cc0+1];
    for(int nt=0;nt<16;nt++){
      int p0=ph+nt*8;
      const __nv_bfloat16* bs=xs+(p0+grp)*72+2*t4;
      float d00=br0,d01=br0,d02=bp0,d03=bp0;
      float d10=br1,d11=br1,d12=bp1,d13=bp1;
#pragma unroll
      for(int k=0;k<4;k++){
        uint32_t b0=*(const uint32_t*)(bs+k*16), b1=*(const uint32_t*)(bs+k*16+8);
        mma_bf16(d00,d01,d02,d03,A0[k][0],A0[k][1],A0[k][2],A0[k][3],b0,b1);
        mma_bf16(d10,d11,d12,d13,A1[k][0],A1[k][1],A1[k][2],A1[k][3],b0,b1);
      }
      int px=p0+2*t4;
      *(uint32_t*)&ts[px*72+cc0]    =pkf(d00*d02, d10*d12);
      *(uint32_t*)&ts[(px+1)*72+cc0]=pkf(d01*d03, d11*d13);
    }
  }
  __syncthreads();
  { // stage 2: z = W4 @ gated; out += beta2*(z+b4)
    int m0=(wid&3)*16, ph=(wid>>2)*128;
    uint32_t A[4][4]; loadA(A,g_w4h,m0,grp,t4);
    int cA=m0+grp, cB=m0+grp+8;
    float biA=pw4b[cA],biB=pw4b[cB],beA=beta2[cA],beB=beta2[cB];
    float* opA=out+(size_t)(n*64+cA)*HW+base;
    float* opB=out+(size_t)(n*64+cB)*HW+base;
    for(int nt=0;nt<16;nt++){
      int p0=ph+nt*8;
      const __nv_bfloat16* bs=ts+(p0+grp)*72+2*t4;
      float d0=0,d1=0,d2=0,d3=0;
#pragma unroll
      for(int k=0;k<4;k++){
        uint32_t b0=*(const uint32_t*)(bs+k*16), b1=*(const uint32_t*)(bs+k*16+8);
        mma_bf16(d0,d1,d2,d3,A[k][0],A[k][1],A[k][2],A[k][3],b0,b1);
      }
      int px=p0+2*t4;
      float2 xa=*(const float2*)(opA+px), xb=*(const float2*)(opB+px);
      float o0=xa.x+beA*(d0+biA), o1=xa.y+beA*(d1+biA);
      float o2=xb.x+beB*(d2+biB), o3=xb.y+beB*(d3+biB);
      *(float2*)(opA+px)=make_float2(o0,o1);
      *(float2*)(opB+px)=make_float2(o2,o3);
    }
  }
}

extern "C" void kernel_launch(void* const* d_in, const int* in_sizes, int n_in,
                              void* d_out, int out_size){
  const float* x    =(const float*)d_in[0];
  const float* ln1w =(const float*)d_in[1];
  const float* ln1b =(const float*)d_in[2];
  const float* pw1w =(const float*)d_in[3];
  const float* pw1b =(const float*)d_in[4];
  const float* dww  =(const float*)d_in[5];
  const float* dwb  =(const float*)d_in[6];
  const float* scaw =(const float*)d_in[7];
  const float* scab =(const float*)d_in[8];
  const float* pw2w =(const float*)d_in[9];
  const float* pw2b =(const float*)d_in[10];
  const float* ln2w =(const float*)d_in[11];
  const float* ln2b =(const float*)d_in[12];
  const float* pw3w =(const float*)d_in[13];
  const float* pw3b =(const float*)d_in[14];
  const float* pw4w =(const float*)d_in[15];
  const float* pw4b =(const float*)d_in[16];
  const float* beta1=(const float*)d_in[17];
  const float* beta2=(const float*)d_in[18];
  float* out=(float*)d_out;

  cudaFuncSetAttribute(k3, cudaFuncAttributeMaxDynamicSharedMemorySize, K3_SMEM);
  cudaFuncSetAttribute(k7, cudaFuncAttributeMaxDynamicSharedMemorySize, K7_SMEM);

  k1 <<<512,256>>>(x,ln1w,ln1b,pw1w,pw1b,pw4w);
  k3 <<<dim3(8,32,8),256,K3_SMEM>>>(x,dww,dwb,scaw,scab,pw2w);
  k5 <<<dim3(256,8),256>>>(x,pw2b,beta1,out,ln2w,ln2b,pw3w,pw3b);
  k7 <<<dim3(256,8),256,K7_SMEM>>>(pw4b,beta2,out);
}